// round 2
// baseline (speedup 1.0000x reference)
#include <cuda_runtime.h>
#include <cstdint>
#include <math.h>

#define NN 100000
#define NE 1600000
#define NG 512

// ---------------- device scratch (static, no allocations) ----------------
__device__ __align__(16) float g_buf0[NN * 128];
__device__ __align__(16) float g_buf1[NN * 128];
__device__ __align__(16) float g_bufH[NN * 128];
__device__ float g_deg[NN];
__device__ float g_dinv[NN];
__device__ int   g_src[NE];
__device__ int   g_dst[NE];
__device__ float g_norm[NE];
__device__ __align__(16) float g_pool[NG * 64];
__device__ float g_cnt[NG];
__device__ int   g_e32;   // 1 if edge_index is int32, 0 if int64
__device__ int   g_b32;   // 1 if batch is int32, 0 if int64

// ---------------- small helpers ----------------
__device__ __forceinline__ void red_add_v4(float* p, float a, float b, float c, float d) {
    asm volatile("red.global.add.v4.f32 [%0], {%1,%2,%3,%4};"
                 :: "l"(p), "f"(a), "f"(b), "f"(c), "f"(d) : "memory");
}

// ---------------- dtype detection ----------------
// If the index arrays are int64, all values < 2^31, so every odd 32-bit word
// (high half) is zero. If int32, odd words are real indices -> mostly nonzero.
// Sample 4096 odd words spread across each array; OR-reduce.
__global__ void k_detect(const unsigned* __restrict__ e, const unsigned* __restrict__ b) {
    __shared__ unsigned se[256], sb[256];
    int t = threadIdx.x;
    unsigned ae = 0, ab = 0;
    const int SE = (2 * NE) / 4096;   // 781
    const int SB = NN / 4096;         // 24
    for (int i = t; i < 4096; i += 256) {
        ae |= e[(i * SE) | 1];
        ab |= b[(i * SB) | 1];
    }
    se[t] = ae; sb[t] = ab;
    __syncthreads();
    for (int s = 128; s; s >>= 1) {
        if (t < s) { se[t] |= se[t + s]; sb[t] |= sb[t + s]; }
        __syncthreads();
    }
    if (t == 0) { g_e32 = (se[0] != 0); g_b32 = (sb[0] != 0); }
}

// zero deg + pool + cnt each replay (graph replays must be idempotent)
__global__ void k_zero() {
    int i = blockIdx.x * blockDim.x + threadIdx.x;
    if (i < NN) g_deg[i] = 0.0f;
    if (i < NG * 64) g_pool[i] = 0.0f;
    if (i < NG) g_cnt[i] = 0.0f;
}

// degree + index conversion (dtype-adaptive)
__global__ void k_deg(const void* __restrict__ ei) {
    int e = blockIdx.x * blockDim.x + threadIdx.x;
    if (e >= NE) return;
    int s, d;
    if (g_e32) {
        const int* p = (const int*)ei;
        s = p[e]; d = p[NE + e];
    } else {
        const long long* p = (const long long*)ei;
        s = (int)p[e]; d = (int)p[NE + e];
    }
    g_src[e] = s;
    g_dst[e] = d;
    atomicAdd(&g_deg[d], 1.0f);
}

__global__ void k_dinv() {
    int n = blockIdx.x * blockDim.x + threadIdx.x;
    if (n < NN) g_dinv[n] = 1.0f / sqrtf(g_deg[n] + 1.0f);
}

__global__ void k_norm() {
    int e = blockIdx.x * blockDim.x + threadIdx.x;
    if (e < NE) g_norm[e] = g_dinv[g_src[e]] * g_dinv[g_dst[e]];
}

// ---------------- dense GEMM: H = act(X) @ W ; O = H/deg + b ----------------
// block: (DOUT/4, 4) threads, 32 rows per block. N_NODES = 3125 * 32 exactly.
template<int DIN, int DOUT, bool RELU>
__global__ void k_gemm(const float* __restrict__ X, const float* __restrict__ W,
                       const float* __restrict__ B,
                       float* __restrict__ H, float* __restrict__ O) {
    constexpr int BX = DOUT / 4;
    constexpr int NT = BX * 4;
    extern __shared__ float sm[];
    float* Ws = sm;                 // DIN*DOUT
    float* xs = sm + DIN * DOUT;    // 32*DIN
    const int tx = threadIdx.x;
    const int ty = threadIdx.y;
    const int tid = ty * BX + tx;
    const int row0 = blockIdx.x * 32;

    float4* Ws4 = (float4*)Ws;
    const float4* W4 = (const float4*)W;
    #pragma unroll 4
    for (int i = tid; i < DIN * DOUT / 4; i += NT) Ws4[i] = W4[i];
    for (int i = tid; i < 32 * DIN; i += NT) {
        float v = X[(size_t)row0 * DIN + i];
        if (RELU) v = fmaxf(v, 0.0f);
        xs[i] = v;
    }
    __syncthreads();

    float acc[8][4];
    #pragma unroll
    for (int r = 0; r < 8; r++) { acc[r][0] = acc[r][1] = acc[r][2] = acc[r][3] = 0.0f; }

    #pragma unroll 4
    for (int k = 0; k < DIN; k++) {
        float4 wv = Ws4[k * BX + tx];
        #pragma unroll
        for (int r = 0; r < 8; r++) {
            float xv = xs[(ty * 8 + r) * DIN + k];
            acc[r][0] += xv * wv.x;
            acc[r][1] += xv * wv.y;
            acc[r][2] += xv * wv.z;
            acc[r][3] += xv * wv.w;
        }
    }

    float4 bv = ((const float4*)B)[tx];
    #pragma unroll
    for (int r = 0; r < 8; r++) {
        int row = row0 + ty * 8 + r;
        float dv = g_dinv[row];
        float sl = dv * dv;   // self-loop weight = 1/deg
        float4 h = make_float4(acc[r][0], acc[r][1], acc[r][2], acc[r][3]);
        ((float4*)H)[(size_t)row * BX + tx] = h;
        float4 o = make_float4(h.x * sl + bv.x, h.y * sl + bv.y,
                               h.z * sl + bv.z, h.w * sl + bv.w);
        ((float4*)O)[(size_t)row * BX + tx] = o;
    }
}

// ---------------- edge scatter: O[dst] += norm * H[src] ----------------
template<int DOUT>
__global__ void k_scatter(const float* __restrict__ H, float* __restrict__ O) {
    constexpr int TPE = DOUT / 4;   // float4 lanes per edge
    int gid = blockIdx.x * blockDim.x + threadIdx.x;
    int e = gid / TPE;
    int c = gid % TPE;
    if (e >= NE) return;
    float nm = g_norm[e];
    int s = g_src[e];
    int d = g_dst[e];
    float4 v = ((const float4*)H)[(size_t)s * TPE + c];
    float* op = O + (size_t)d * DOUT + c * 4;
    red_add_v4(op, v.x * nm, v.y * nm, v.z * nm, v.w * nm);
}

// ---------------- mean-pool scatter over graphs (dtype-adaptive batch) ------
__global__ void k_pool(const float* __restrict__ Hf, const void* __restrict__ batch) {
    int gid = blockIdx.x * blockDim.x + threadIdx.x;
    int n = gid / 16;
    int c = gid % 16;
    if (n >= NN) return;
    int g;
    if (g_b32) g = ((const int*)batch)[n];
    else       g = (int)((const long long*)batch)[n];
    float4 v = ((const float4*)Hf)[(size_t)n * 16 + c];
    red_add_v4(&g_pool[g * 64 + c * 4], v.x, v.y, v.z, v.w);
    if (c == 0) atomicAdd(&g_cnt[g], 1.0f);
}

// ---------------- final MLP: [G,64] -> relu(32) -> 9 ----------------
__global__ void k_mlp(const float* __restrict__ Wl1, const float* __restrict__ bl1,
                      const float* __restrict__ Wl2, const float* __restrict__ bl2,
                      float* __restrict__ out) {
    __shared__ float mean[64];
    __shared__ float hid[32];
    int g = blockIdx.x;
    int t = threadIdx.x;
    float cnt = fmaxf(g_cnt[g], 1.0f);
    mean[t] = g_pool[g * 64 + t] / cnt;
    __syncthreads();
    if (t < 32) {
        float s = bl1[t];
        #pragma unroll 8
        for (int k = 0; k < 64; k++) s += mean[k] * Wl1[k * 32 + t];
        hid[t] = fmaxf(s, 0.0f);
    }
    __syncthreads();
    if (t < 9) {
        float s = bl2[t];
        #pragma unroll 8
        for (int k = 0; k < 32; k++) s += hid[k] * Wl2[k * 9 + t];
        out[g * 9 + t] = s;
    }
}

// ---------------- launch ----------------
extern "C" void kernel_launch(void* const* d_in, const int* in_sizes, int n_in,
                              void* d_out, int out_size) {
    const float* x     = (const float*)d_in[0];
    const void*  ei    = d_in[1];
    const void*  batch = d_in[2];
    const float* W1 = (const float*)d_in[3];  const float* b1 = (const float*)d_in[4];
    const float* W2 = (const float*)d_in[5];  const float* b2 = (const float*)d_in[6];
    const float* W3 = (const float*)d_in[7];  const float* b3 = (const float*)d_in[8];
    const float* W4 = (const float*)d_in[9];  const float* b4 = (const float*)d_in[10];
    const float* Wl1 = (const float*)d_in[11]; const float* bl1 = (const float*)d_in[12];
    const float* Wl2 = (const float*)d_in[13]; const float* bl2 = (const float*)d_in[14];
    float* out = (float*)d_out;

    float *buf0, *buf1, *bufH;
    cudaGetSymbolAddress((void**)&buf0, g_buf0);
    cudaGetSymbolAddress((void**)&buf1, g_buf1);
    cudaGetSymbolAddress((void**)&bufH, g_bufH);

    const int smem1 = (3   * 128 + 32 * 3  ) * 4;   // layer 1
    const int smem2 = (128 * 128 + 32 * 128) * 4;   // layers 2,3 (80 KB)
    const int smem3 = (128 * 64  + 32 * 128) * 4;   // layer 4 (48 KB)
    cudaFuncSetAttribute((const void*)k_gemm<128, 128, true>,
                         cudaFuncAttributeMaxDynamicSharedMemorySize, smem2);
    cudaFuncSetAttribute((const void*)k_gemm<128, 64, true>,
                         cudaFuncAttributeMaxDynamicSharedMemorySize, smem3);

    const int ROWS_GRID = NN / 32;          // 3125 (exact)
    dim3 gblk128(32, 4), gblk64(16, 4);

    k_detect<<<1, 256>>>((const unsigned*)ei, (const unsigned*)batch);
    k_zero<<<(NN + 255) / 256, 256>>>();
    k_deg<<<NE / 256, 256>>>(ei);
    k_dinv<<<(NN + 255) / 256, 256>>>();
    k_norm<<<NE / 256, 256>>>();

    // layer 1: 3 -> 128 (no input relu)
    k_gemm<3, 128, false><<<ROWS_GRID, gblk128, smem1>>>(x, W1, b1, bufH, buf0);
    k_scatter<128><<<(NE * 32) / 256, 256>>>(bufH, buf0);
    // layer 2: 128 -> 128
    k_gemm<128, 128, true><<<ROWS_GRID, gblk128, smem2>>>(buf0, W2, b2, bufH, buf1);
    k_scatter<128><<<(NE * 32) / 256, 256>>>(bufH, buf1);
    // layer 3: 128 -> 128
    k_gemm<128, 128, true><<<ROWS_GRID, gblk128, smem2>>>(buf1, W3, b3, bufH, buf0);
    k_scatter<128><<<(NE * 32) / 256, 256>>>(bufH, buf0);
    // layer 4: 128 -> 64 (no output relu)
    k_gemm<128, 64, true><<<ROWS_GRID, gblk64, smem3>>>(buf0, W4, b4, bufH, buf1);
    k_scatter<64><<<(NE * 16) / 256, 256>>>(bufH, buf1);

    // mean-pool + MLP head
    k_pool<<<(NN * 16) / 256, 256>>>(buf1, batch);
    k_mlp<<<NG, 64>>>(Wl1, bl1, Wl2, bl2, out);
}

// round 3
// speedup vs baseline: 1.8632x; 1.8632x over previous
#include <cuda_runtime.h>
#include <cstdint>
#include <math.h>

#define NN 100000
#define NE 1600000
#define NG 512
#define NB_SCAN 196   // ceil(NN/512)

// ---------------- device scratch (static, no allocations) ----------------
__device__ __align__(16) float g_buf0[NN * 128];
__device__ __align__(16) float g_buf1[NN * 128];
__device__ __align__(16) float g_bufA[NN * 3];
__device__ int   g_ideg[NN];
__device__ float g_dinv[NN];
__device__ int   g_src[NE];
__device__ int   g_dst[NE];
__device__ int   g_csrc[NE];
__device__ float g_cnorm[NE];
__device__ int   g_rowptr[NN + 1];
__device__ int   g_cur[NN];
__device__ int   g_bsum[256];
__device__ __align__(16) float g_pool[NG * 64];
__device__ float g_cnt[NG];
__device__ int   g_e32;   // 1 if edge_index is int32, 0 if int64
__device__ int   g_b32;   // 1 if batch is int32, 0 if int64

__device__ __forceinline__ void red_add_v4(float* p, float a, float b, float c, float d) {
    asm volatile("red.global.add.v4.f32 [%0], {%1,%2,%3,%4};"
                 :: "l"(p), "f"(a), "f"(b), "f"(c), "f"(d) : "memory");
}

// ---------------- dtype detection (int32 vs int64 index arrays) ----------
__global__ void k_detect(const unsigned* __restrict__ e, const unsigned* __restrict__ b) {
    __shared__ unsigned se[256], sb[256];
    int t = threadIdx.x;
    unsigned ae = 0, ab = 0;
    const int SE = (2 * NE) / 4096;
    const int SB = NN / 4096;
    for (int i = t; i < 4096; i += 256) {
        ae |= e[(i * SE) | 1];
        ab |= b[(i * SB) | 1];
    }
    se[t] = ae; sb[t] = ab;
    __syncthreads();
    for (int s = 128; s; s >>= 1) {
        if (t < s) { se[t] |= se[t + s]; sb[t] |= sb[t + s]; }
        __syncthreads();
    }
    if (t == 0) { g_e32 = (se[0] != 0); g_b32 = (sb[0] != 0); }
}

__global__ void k_zero() {
    int i = blockIdx.x * blockDim.x + threadIdx.x;
    if (i < NN) g_ideg[i] = 0;
    if (i < NG * 64) g_pool[i] = 0.0f;
    if (i < NG) g_cnt[i] = 0.0f;
}

// degree count + index conversion
__global__ void k_deg(const void* __restrict__ ei) {
    int e = blockIdx.x * blockDim.x + threadIdx.x;
    if (e >= NE) return;
    int s, d;
    if (g_e32) {
        const int* p = (const int*)ei;
        s = p[e]; d = p[NE + e];
    } else {
        const long long* p = (const long long*)ei;
        s = (int)p[e]; d = (int)p[NE + e];
    }
    g_src[e] = s;
    g_dst[e] = d;
    atomicAdd(&g_ideg[d], 1);
}

// ---------------- 2-level exclusive scan of degrees -> rowptr ------------
__global__ void k_scan1() {
    __shared__ int sm[512];
    int t = threadIdx.x;
    int i = blockIdx.x * 512 + t;
    int v = (i < NN) ? g_ideg[i] : 0;
    sm[t] = v;
    __syncthreads();
    for (int off = 1; off < 512; off <<= 1) {
        int x = 0;
        if (t >= off) x = sm[t - off];
        __syncthreads();
        if (t >= off) sm[t] += x;
        __syncthreads();
    }
    if (i < NN) g_rowptr[i] = sm[t] - v;          // exclusive within block
    if (t == 511) g_bsum[blockIdx.x] = sm[511];   // block total
}

__global__ void k_scan2() {
    __shared__ int sm[256];
    int t = threadIdx.x;
    int v = (t < NB_SCAN) ? g_bsum[t] : 0;
    sm[t] = v;
    __syncthreads();
    for (int off = 1; off < 256; off <<= 1) {
        int x = 0;
        if (t >= off) x = sm[t - off];
        __syncthreads();
        if (t >= off) sm[t] += x;
        __syncthreads();
    }
    if (t < NB_SCAN) g_bsum[t] = sm[t] - v;       // exclusive block offsets
}

__global__ void k_scan3() {
    int i = blockIdx.x * blockDim.x + threadIdx.x;
    if (i < NN) {
        int r = g_rowptr[i] + g_bsum[i >> 9];
        g_rowptr[i] = r;
        g_cur[i] = r;
        g_dinv[i] = rsqrtf((float)g_ideg[i] + 1.0f);
    }
    if (i == 0) g_rowptr[NN] = NE;
}

// scatter edges into CSR (sorted by dst), norm = dinv[src]*dinv[dst]
__global__ void k_build() {
    int e = blockIdx.x * blockDim.x + threadIdx.x;
    if (e >= NE) return;
    int s = g_src[e];
    int d = g_dst[e];
    int pos = atomicAdd(&g_cur[d], 1);
    g_csrc[pos] = s;
    g_cnorm[pos] = g_dinv[s] * g_dinv[d];
}

// ---------------- layer-1 input aggregation: A = Â x (dim 3) -------------
__global__ void k_agg3(const float* __restrict__ x) {
    int d = blockIdx.x * blockDim.x + threadIdx.x;
    if (d >= NN) return;
    int p = g_rowptr[d], pe = g_rowptr[d + 1];
    float a0 = 0.f, a1 = 0.f, a2 = 0.f;
    for (; p + 2 <= pe; p += 2) {
        int s0 = g_csrc[p], s1 = g_csrc[p + 1];
        float n0 = g_cnorm[p], n1 = g_cnorm[p + 1];
        float x00 = x[s0 * 3], x01 = x[s0 * 3 + 1], x02 = x[s0 * 3 + 2];
        float x10 = x[s1 * 3], x11 = x[s1 * 3 + 1], x12 = x[s1 * 3 + 2];
        a0 += n0 * x00 + n1 * x10;
        a1 += n0 * x01 + n1 * x11;
        a2 += n0 * x02 + n1 * x12;
    }
    for (; p < pe; p++) {
        int s = g_csrc[p]; float nm = g_cnorm[p];
        a0 += nm * x[s * 3]; a1 += nm * x[s * 3 + 1]; a2 += nm * x[s * 3 + 2];
    }
    float dv = g_dinv[d], sl = dv * dv;
    g_bufA[d * 3 + 0] = a0 + sl * x[d * 3 + 0];
    g_bufA[d * 3 + 1] = a1 + sl * x[d * 3 + 1];
    g_bufA[d * 3 + 2] = a2 + sl * x[d * 3 + 2];
}

// ---------------- dense GEMM: H = X @ W (+b, relu optional) --------------
template<int DIN, int DOUT, bool BIAS, bool RELU>
__global__ void k_gemm(const float* __restrict__ X, const float* __restrict__ W,
                       const float* __restrict__ B, float* __restrict__ H) {
    constexpr int BX = DOUT / 4;
    constexpr int NT = BX * 4;
    extern __shared__ float sm[];
    float* Ws = sm;                 // DIN*DOUT
    float* xs = sm + DIN * DOUT;    // 32*DIN
    const int tx = threadIdx.x;
    const int ty = threadIdx.y;
    const int tid = ty * BX + tx;
    const int row0 = blockIdx.x * 32;

    float4* Ws4 = (float4*)Ws;
    const float4* W4 = (const float4*)W;
    #pragma unroll 4
    for (int i = tid; i < DIN * DOUT / 4; i += NT) Ws4[i] = W4[i];
    for (int i = tid; i < 32 * DIN; i += NT)
        xs[i] = X[(size_t)row0 * DIN + i];
    __syncthreads();

    float acc[8][4];
    #pragma unroll
    for (int r = 0; r < 8; r++) { acc[r][0] = acc[r][1] = acc[r][2] = acc[r][3] = 0.0f; }

    #pragma unroll 4
    for (int k = 0; k < DIN; k++) {
        float4 wv = Ws4[k * BX + tx];
        #pragma unroll
        for (int r = 0; r < 8; r++) {
            float xv = xs[(ty * 8 + r) * DIN + k];
            acc[r][0] += xv * wv.x;
            acc[r][1] += xv * wv.y;
            acc[r][2] += xv * wv.z;
            acc[r][3] += xv * wv.w;
        }
    }

    float4 bv = make_float4(0.f, 0.f, 0.f, 0.f);
    if (BIAS) bv = ((const float4*)B)[tx];
    #pragma unroll
    for (int r = 0; r < 8; r++) {
        int row = row0 + ty * 8 + r;
        float4 h = make_float4(acc[r][0] + bv.x, acc[r][1] + bv.y,
                               acc[r][2] + bv.z, acc[r][3] + bv.w);
        if (RELU) {
            h.x = fmaxf(h.x, 0.f); h.y = fmaxf(h.y, 0.f);
            h.z = fmaxf(h.z, 0.f); h.w = fmaxf(h.w, 0.f);
        }
        ((float4*)H)[(size_t)row * BX + tx] = h;
    }
}

// ---------------- CSR aggregation, dim 128: warp per row ------------------
// O[d] = relu( sum_e norm*H[src] + (1/deg)*H[d] + b )
template<bool RELU>
__global__ void k_agg128(const float* __restrict__ H, const float* __restrict__ B,
                         float* __restrict__ O) {
    int warp = (blockIdx.x * blockDim.x + threadIdx.x) >> 5;
    int lane = threadIdx.x & 31;
    if (warp >= NN) return;
    int d = warp;
    const float4* H4 = (const float4*)H;
    int p = g_rowptr[d], pe = g_rowptr[d + 1];
    float4 acc = make_float4(0.f, 0.f, 0.f, 0.f);
    for (; p + 4 <= pe; p += 4) {
        int s0 = g_csrc[p],     s1 = g_csrc[p + 1];
        int s2 = g_csrc[p + 2], s3 = g_csrc[p + 3];
        float n0 = g_cnorm[p],     n1 = g_cnorm[p + 1];
        float n2 = g_cnorm[p + 2], n3 = g_cnorm[p + 3];
        float4 v0 = H4[(size_t)s0 * 32 + lane];
        float4 v1 = H4[(size_t)s1 * 32 + lane];
        float4 v2 = H4[(size_t)s2 * 32 + lane];
        float4 v3 = H4[(size_t)s3 * 32 + lane];
        acc.x += n0 * v0.x + n1 * v1.x + n2 * v2.x + n3 * v3.x;
        acc.y += n0 * v0.y + n1 * v1.y + n2 * v2.y + n3 * v3.y;
        acc.z += n0 * v0.z + n1 * v1.z + n2 * v2.z + n3 * v3.z;
        acc.w += n0 * v0.w + n1 * v1.w + n2 * v2.w + n3 * v3.w;
    }
    for (; p < pe; p++) {
        int s = g_csrc[p]; float nm = g_cnorm[p];
        float4 v = H4[(size_t)s * 32 + lane];
        acc.x += nm * v.x; acc.y += nm * v.y; acc.z += nm * v.z; acc.w += nm * v.w;
    }
    float dv = g_dinv[d], sl = dv * dv;
    float4 hd = H4[(size_t)d * 32 + lane];
    float4 bv = ((const float4*)B)[lane];
    acc.x += sl * hd.x + bv.x;
    acc.y += sl * hd.y + bv.y;
    acc.z += sl * hd.z + bv.z;
    acc.w += sl * hd.w + bv.w;
    if (RELU) {
        acc.x = fmaxf(acc.x, 0.f); acc.y = fmaxf(acc.y, 0.f);
        acc.z = fmaxf(acc.z, 0.f); acc.w = fmaxf(acc.w, 0.f);
    }
    ((float4*)O)[(size_t)d * 32 + lane] = acc;
}

// ---------------- final agg (dim 64) fused with mean-pool scatter --------
__global__ void k_agg64_pool(const float* __restrict__ H, const float* __restrict__ B,
                             const void* __restrict__ batch) {
    int gt = blockIdx.x * blockDim.x + threadIdx.x;
    int d = gt >> 4;            // 16 lanes (float4) per row
    int c = gt & 15;
    if (d >= NN) return;
    const float4* H4 = (const float4*)H;
    int p = g_rowptr[d], pe = g_rowptr[d + 1];
    float4 acc = make_float4(0.f, 0.f, 0.f, 0.f);
    for (; p + 4 <= pe; p += 4) {
        int s0 = g_csrc[p],     s1 = g_csrc[p + 1];
        int s2 = g_csrc[p + 2], s3 = g_csrc[p + 3];
        float n0 = g_cnorm[p],     n1 = g_cnorm[p + 1];
        float n2 = g_cnorm[p + 2], n3 = g_cnorm[p + 3];
        float4 v0 = H4[(size_t)s0 * 16 + c];
        float4 v1 = H4[(size_t)s1 * 16 + c];
        float4 v2 = H4[(size_t)s2 * 16 + c];
        float4 v3 = H4[(size_t)s3 * 16 + c];
        acc.x += n0 * v0.x + n1 * v1.x + n2 * v2.x + n3 * v3.x;
        acc.y += n0 * v0.y + n1 * v1.y + n2 * v2.y + n3 * v3.y;
        acc.z += n0 * v0.z + n1 * v1.z + n2 * v2.z + n3 * v3.z;
        acc.w += n0 * v0.w + n1 * v1.w + n2 * v2.w + n3 * v3.w;
    }
    for (; p < pe; p++) {
        int s = g_csrc[p]; float nm = g_cnorm[p];
        float4 v = H4[(size_t)s * 16 + c];
        acc.x += nm * v.x; acc.y += nm * v.y; acc.z += nm * v.z; acc.w += nm * v.w;
    }
    float dv = g_dinv[d], sl = dv * dv;
    float4 hd = H4[(size_t)d * 16 + c];
    float4 bv = ((const float4*)B)[c];
    acc.x += sl * hd.x + bv.x;
    acc.y += sl * hd.y + bv.y;
    acc.z += sl * hd.z + bv.z;
    acc.w += sl * hd.w + bv.w;
    int g;
    if (g_b32) g = ((const int*)batch)[d];
    else       g = (int)((const long long*)batch)[d];
    red_add_v4(&g_pool[g * 64 + c * 4], acc.x, acc.y, acc.z, acc.w);
    if (c == 0) atomicAdd(&g_cnt[g], 1.0f);
}

// ---------------- final MLP: [G,64] -> relu(32) -> 9 ----------------
__global__ void k_mlp(const float* __restrict__ Wl1, const float* __restrict__ bl1,
                      const float* __restrict__ Wl2, const float* __restrict__ bl2,
                      float* __restrict__ out) {
    __shared__ float mean[64];
    __shared__ float hid[32];
    int g = blockIdx.x;
    int t = threadIdx.x;
    float cnt = fmaxf(g_cnt[g], 1.0f);
    mean[t] = g_pool[g * 64 + t] / cnt;
    __syncthreads();
    if (t < 32) {
        float s = bl1[t];
        #pragma unroll 8
        for (int k = 0; k < 64; k++) s += mean[k] * Wl1[k * 32 + t];
        hid[t] = fmaxf(s, 0.0f);
    }
    __syncthreads();
    if (t < 9) {
        float s = bl2[t];
        #pragma unroll 8
        for (int k = 0; k < 32; k++) s += hid[k] * Wl2[k * 9 + t];
        out[g * 9 + t] = s;
    }
}

// ---------------- launch ----------------
extern "C" void kernel_launch(void* const* d_in, const int* in_sizes, int n_in,
                              void* d_out, int out_size) {
    const float* x     = (const float*)d_in[0];
    const void*  ei    = d_in[1];
    const void*  batch = d_in[2];
    const float* W1 = (const float*)d_in[3];  const float* b1 = (const float*)d_in[4];
    const float* W2 = (const float*)d_in[5];  const float* b2 = (const float*)d_in[6];
    const float* W3 = (const float*)d_in[7];  const float* b3 = (const float*)d_in[8];
    const float* W4 = (const float*)d_in[9];  const float* b4 = (const float*)d_in[10];
    const float* Wl1 = (const float*)d_in[11]; const float* bl1 = (const float*)d_in[12];
    const float* Wl2 = (const float*)d_in[13]; const float* bl2 = (const float*)d_in[14];
    float* out = (float*)d_out;

    float *buf0, *buf1, *bufA;
    cudaGetSymbolAddress((void**)&buf0, g_buf0);
    cudaGetSymbolAddress((void**)&buf1, g_buf1);
    cudaGetSymbolAddress((void**)&bufA, g_bufA);

    const int smem1 = (3   * 128 + 32 * 3  ) * 4;
    const int smem2 = (128 * 128 + 32 * 128) * 4;   // 80 KB
    const int smem3 = (128 * 64  + 32 * 128) * 4;   // 48 KB
    cudaFuncSetAttribute((const void*)k_gemm<128, 128, false, false>,
                         cudaFuncAttributeMaxDynamicSharedMemorySize, smem2);
    cudaFuncSetAttribute((const void*)k_gemm<128, 64, false, false>,
                         cudaFuncAttributeMaxDynamicSharedMemorySize, smem3);

    const int ROWS_GRID = NN / 32;          // 3125
    dim3 gblk128(32, 4), gblk64(16, 4);

    // preprocessing: dtype detect, CSR build
    k_detect<<<1, 256>>>((const unsigned*)ei, (const unsigned*)batch);
    k_zero<<<(NN + 255) / 256, 256>>>();
    k_deg<<<NE / 256, 256>>>(ei);
    k_scan1<<<NB_SCAN, 512>>>();
    k_scan2<<<1, 256>>>();
    k_scan3<<<(NN + 255) / 256, 256>>>();
    k_build<<<NE / 256, 256>>>();

    // layer 1 (reordered): A = Â x (dim 3), then X2 = relu(A @ W1 + b1)
    k_agg3<<<(NN + 255) / 256, 256>>>(x);
    k_gemm<3, 128, true, true><<<ROWS_GRID, gblk128, smem1>>>(bufA, W1, b1, buf0);

    // layer 2: H2 = X2 @ W2 ; X3 = relu(Â H2 + b2)
    k_gemm<128, 128, false, false><<<ROWS_GRID, gblk128, smem2>>>(buf0, W2, b2, buf1);
    k_agg128<true><<<12500, 256>>>(buf1, b2, buf0);

    // layer 3
    k_gemm<128, 128, false, false><<<ROWS_GRID, gblk128, smem2>>>(buf0, W3, b3, buf1);
    k_agg128<true><<<12500, 256>>>(buf1, b3, buf0);

    // layer 4: H4 = X4 @ W4 (dim 64); agg + mean-pool fused
    k_gemm<128, 64, false, false><<<ROWS_GRID, gblk64, smem3>>>(buf0, W4, b4, buf1);
    k_agg64_pool<<<(NN * 16 + 255) / 256, 256>>>(buf1, b4, batch);

    k_mlp<<<NG, 64>>>(Wl1, bl1, Wl2, bl2, out);
}

// round 4
// speedup vs baseline: 3.1088x; 1.6685x over previous
#include <cuda_runtime.h>
#include <cuda_bf16.h>
#include <cstdint>
#include <math.h>

#define NN 100000
#define NE 1600000
#define NG 512
#define NB_SCAN 196   // ceil(NN/512)

// ---------------- device scratch (static, no allocations) ----------------
__device__ __align__(16) float g_buf1[NN * 128];          // H (gemm out, f32)
__device__ __align__(16) __nv_bfloat16 g_Xhi[NN * 128];   // activation hi
__device__ __align__(16) __nv_bfloat16 g_Xlo[NN * 128];   // activation lo
__device__ __align__(16) float g_bufA[NN * 3];
__device__ __align__(16) __nv_bfloat16 g_W2hi[16384], g_W2lo[16384];
__device__ __align__(16) __nv_bfloat16 g_W3hi[16384], g_W3lo[16384];
__device__ __align__(16) __nv_bfloat16 g_W4hi[8192],  g_W4lo[8192];
__device__ int   g_ideg[NN];
__device__ float g_dinv[NN];
__device__ int   g_src[NE];
__device__ int   g_dst[NE];
__device__ int   g_csrc[NE];
__device__ float g_cnorm[NE];
__device__ int   g_rowptr[NN + 1];
__device__ int   g_cur[NN];
__device__ int   g_bsum[256];
__device__ __align__(16) float g_pool[NG * 64];
__device__ float g_cnt[NG];
__device__ int   g_e32;
__device__ int   g_b32;

// ---------------- helpers ----------------
__device__ __forceinline__ void red_add_v4(float* p, float a, float b, float c, float d) {
    asm volatile("red.global.add.v4.f32 [%0], {%1,%2,%3,%4};"
                 :: "l"(p), "f"(a), "f"(b), "f"(c), "f"(d) : "memory");
}
__device__ __forceinline__ unsigned short f2bf(float f) {
    __nv_bfloat16 b = __float2bfloat16(f);
    return *(unsigned short*)&b;
}
__device__ __forceinline__ float bf2f(unsigned short u) {
    __nv_bfloat16 b = *(__nv_bfloat16*)&u;
    return __bfloat162float(b);
}
__device__ __forceinline__ uint32_t sptr(const void* p) {
    return (uint32_t)__cvta_generic_to_shared(p);
}
__device__ __forceinline__ void ldsm_x4(uint32_t (&r)[4], uint32_t a) {
    asm volatile("ldmatrix.sync.aligned.m8n8.x4.shared.b16 {%0,%1,%2,%3}, [%4];"
                 : "=r"(r[0]), "=r"(r[1]), "=r"(r[2]), "=r"(r[3]) : "r"(a));
}
__device__ __forceinline__ void ldsm_x2t(uint32_t (&r)[2], uint32_t a) {
    asm volatile("ldmatrix.sync.aligned.m8n8.x2.trans.shared.b16 {%0,%1}, [%2];"
                 : "=r"(r[0]), "=r"(r[1]) : "r"(a));
}
__device__ __forceinline__ void mma_bf16(float (&d)[4], const uint32_t (&a)[4],
                                         const uint32_t (&b)[2]) {
    asm volatile("mma.sync.aligned.m16n8k16.row.col.f32.bf16.bf16.f32 "
                 "{%0,%1,%2,%3}, {%4,%5,%6,%7}, {%8,%9}, {%0,%1,%2,%3};"
                 : "+f"(d[0]), "+f"(d[1]), "+f"(d[2]), "+f"(d[3])
                 : "r"(a[0]), "r"(a[1]), "r"(a[2]), "r"(a[3]), "r"(b[0]), "r"(b[1]));
}

// ---------------- dtype detection (int32 vs int64 index arrays) ----------
__global__ void k_detect(const unsigned* __restrict__ e, const unsigned* __restrict__ b) {
    __shared__ unsigned se[256], sb[256];
    int t = threadIdx.x;
    unsigned ae = 0, ab = 0;
    const int SE = (2 * NE) / 4096;
    const int SB = NN / 4096;
    for (int i = t; i < 4096; i += 256) {
        ae |= e[(i * SE) | 1];
        ab |= b[(i * SB) | 1];
    }
    se[t] = ae; sb[t] = ab;
    __syncthreads();
    for (int s = 128; s; s >>= 1) {
        if (t < s) { se[t] |= se[t + s]; sb[t] |= sb[t + s]; }
        __syncthreads();
    }
    if (t == 0) { g_e32 = (se[0] != 0); g_b32 = (sb[0] != 0); }
}

__global__ void k_zero() {
    int i = blockIdx.x * blockDim.x + threadIdx.x;
    if (i < NN) g_ideg[i] = 0;
    if (i < NG * 64) g_pool[i] = 0.0f;
    if (i < NG) g_cnt[i] = 0.0f;
}

__global__ void k_deg(const void* __restrict__ ei) {
    int e = blockIdx.x * blockDim.x + threadIdx.x;
    if (e >= NE) return;
    int s, d;
    if (g_e32) {
        const int* p = (const int*)ei;
        s = p[e]; d = p[NE + e];
    } else {
        const long long* p = (const long long*)ei;
        s = (int)p[e]; d = (int)p[NE + e];
    }
    g_src[e] = s;
    g_dst[e] = d;
    atomicAdd(&g_ideg[d], 1);
}

// ---------------- 2-level exclusive scan of degrees -> rowptr ------------
__global__ void k_scan1() {
    __shared__ int sm[512];
    int t = threadIdx.x;
    int i = blockIdx.x * 512 + t;
    int v = (i < NN) ? g_ideg[i] : 0;
    sm[t] = v;
    __syncthreads();
    for (int off = 1; off < 512; off <<= 1) {
        int x = 0;
        if (t >= off) x = sm[t - off];
        __syncthreads();
        if (t >= off) sm[t] += x;
        __syncthreads();
    }
    if (i < NN) g_rowptr[i] = sm[t] - v;
    if (t == 511) g_bsum[blockIdx.x] = sm[511];
}

__global__ void k_scan2() {
    __shared__ int sm[256];
    int t = threadIdx.x;
    int v = (t < NB_SCAN) ? g_bsum[t] : 0;
    sm[t] = v;
    __syncthreads();
    for (int off = 1; off < 256; off <<= 1) {
        int x = 0;
        if (t >= off) x = sm[t - off];
        __syncthreads();
        if (t >= off) sm[t] += x;
        __syncthreads();
    }
    if (t < NB_SCAN) g_bsum[t] = sm[t] - v;
}

__global__ void k_scan3() {
    int i = blockIdx.x * blockDim.x + threadIdx.x;
    if (i < NN) {
        int r = g_rowptr[i] + g_bsum[i >> 9];
        g_rowptr[i] = r;
        g_cur[i] = r;
        g_dinv[i] = rsqrtf((float)g_ideg[i] + 1.0f);
    }
    if (i == 0) g_rowptr[NN] = NE;
}

__global__ void k_build() {
    int e = blockIdx.x * blockDim.x + threadIdx.x;
    if (e >= NE) return;
    int s = g_src[e];
    int d = g_dst[e];
    int pos = atomicAdd(&g_cur[d], 1);
    g_csrc[pos] = s;
    g_cnorm[pos] = g_dinv[s] * g_dinv[d];
}

// ---------------- W split: f32 -> bf16 hi/lo ----------------
__global__ void k_wsplit(const float* __restrict__ W2, const float* __restrict__ W3,
                         const float* __restrict__ W4) {
    int i = blockIdx.x * blockDim.x + threadIdx.x;
    float v; __nv_bfloat16* hi; __nv_bfloat16* lo; int j;
    if (i < 16384)      { j = i;         v = W2[j]; hi = g_W2hi; lo = g_W2lo; }
    else if (i < 32768) { j = i - 16384; v = W3[j]; hi = g_W3hi; lo = g_W3lo; }
    else if (i < 40960) { j = i - 32768; v = W4[j]; hi = g_W4hi; lo = g_W4lo; }
    else return;
    unsigned short h = f2bf(v);
    hi[j] = *(__nv_bfloat16*)&h;
    unsigned short l = f2bf(v - bf2f(h));
    lo[j] = *(__nv_bfloat16*)&l;
}

// ---------------- layer-1 input aggregation: A = Â x (dim 3) -------------
__global__ void k_agg3(const float* __restrict__ x) {
    int d = blockIdx.x * blockDim.x + threadIdx.x;
    if (d >= NN) return;
    int p = g_rowptr[d], pe = g_rowptr[d + 1];
    float a0 = 0.f, a1 = 0.f, a2 = 0.f;
    for (; p + 2 <= pe; p += 2) {
        int s0 = g_csrc[p], s1 = g_csrc[p + 1];
        float n0 = g_cnorm[p], n1 = g_cnorm[p + 1];
        a0 += n0 * x[s0 * 3]     + n1 * x[s1 * 3];
        a1 += n0 * x[s0 * 3 + 1] + n1 * x[s1 * 3 + 1];
        a2 += n0 * x[s0 * 3 + 2] + n1 * x[s1 * 3 + 2];
    }
    for (; p < pe; p++) {
        int s = g_csrc[p]; float nm = g_cnorm[p];
        a0 += nm * x[s * 3]; a1 += nm * x[s * 3 + 1]; a2 += nm * x[s * 3 + 2];
    }
    float dv = g_dinv[d], sl = dv * dv;
    g_bufA[d * 3 + 0] = a0 + sl * x[d * 3 + 0];
    g_bufA[d * 3 + 1] = a1 + sl * x[d * 3 + 1];
    g_bufA[d * 3 + 2] = a2 + sl * x[d * 3 + 2];
}

// ---------------- layer-1 GEMM: X2 = relu(A @ W1 + b1), split output -----
// block (32,4), 32 rows/block, NN = 3125 * 32 exactly.
__global__ void k_gemm3(const float* __restrict__ X, const float* __restrict__ W,
                        const float* __restrict__ B) {
    __shared__ float Ws[3 * 128];
    __shared__ float xs[32 * 3];
    const int tx = threadIdx.x;   // 0..31
    const int ty = threadIdx.y;   // 0..3
    const int tid = ty * 32 + tx;
    const int row0 = blockIdx.x * 32;
    for (int i = tid; i < 3 * 128; i += 128) Ws[i] = W[i];
    if (tid < 96) xs[tid] = X[(size_t)row0 * 3 + tid];
    __syncthreads();

    float4 wv[3];
    #pragma unroll
    for (int k = 0; k < 3; k++) wv[k] = ((const float4*)Ws)[k * 32 + tx];
    float4 bv = ((const float4*)B)[tx];

    #pragma unroll
    for (int r = 0; r < 8; r++) {
        int row = row0 + ty * 8 + r;
        float x0 = xs[(ty * 8 + r) * 3], x1 = xs[(ty * 8 + r) * 3 + 1],
              x2 = xs[(ty * 8 + r) * 3 + 2];
        float4 h;
        h.x = fmaxf(x0 * wv[0].x + x1 * wv[1].x + x2 * wv[2].x + bv.x, 0.f);
        h.y = fmaxf(x0 * wv[0].y + x1 * wv[1].y + x2 * wv[2].y + bv.y, 0.f);
        h.z = fmaxf(x0 * wv[0].z + x1 * wv[1].z + x2 * wv[2].z + bv.z, 0.f);
        h.w = fmaxf(x0 * wv[0].w + x1 * wv[1].w + x2 * wv[2].w + bv.w, 0.f);
        ushort4 hi4, lo4;
        hi4.x = f2bf(h.x); lo4.x = f2bf(h.x - bf2f(hi4.x));
        hi4.y = f2bf(h.y); lo4.y = f2bf(h.y - bf2f(hi4.y));
        hi4.z = f2bf(h.z); lo4.z = f2bf(h.z - bf2f(hi4.z));
        hi4.w = f2bf(h.w); lo4.w = f2bf(h.w - bf2f(hi4.w));
        *(ushort4*)((unsigned short*)g_Xhi + (size_t)row * 128 + tx * 4) = hi4;
        *(ushort4*)((unsigned short*)g_Xlo + (size_t)row * 128 + tx * 4) = lo4;
    }
}

// ---------------- tensor-core GEMM: H = (Xhi+Xlo) @ (Whi+Wlo), f32 out ----
// block: 128 rows x DOUT cols, 256 threads (8 warps: 4 in M, 2 in N), KT=64.
template<int DOUT>
__global__ __launch_bounds__(256) void k_gemm_tc(
    const __nv_bfloat16* __restrict__ Xhi, const __nv_bfloat16* __restrict__ Xlo,
    const __nv_bfloat16* __restrict__ Whi, const __nv_bfloat16* __restrict__ Wlo,
    float* __restrict__ H) {
    constexpr int KT = 64;
    constexpr int XS = 72;            // X smem row stride (bf16)
    constexpr int WS = DOUT + 8;      // W smem row stride
    constexpr int NW = DOUT / 2;      // warp N tile
    constexpr int NF = NW / 8;        // n8 frags per warp
    constexpr int WU4 = DOUT / 8;     // uint4 per W row
    extern __shared__ __nv_bfloat16 smem[];
    __nv_bfloat16* sXhi = smem;
    __nv_bfloat16* sXlo = sXhi + 128 * XS;
    __nv_bfloat16* sWhi = sXlo + 128 * XS;
    __nv_bfloat16* sWlo = sWhi + KT * WS;

    const int tid = threadIdx.x;
    const int wid = tid >> 5;
    const int lane = tid & 31;
    const int warpM = wid & 3;
    const int warpN = wid >> 2;
    const int row0 = blockIdx.x * 128;

    float acc[2][NF][4];
    #pragma unroll
    for (int mi = 0; mi < 2; mi++)
        #pragma unroll
        for (int ni = 0; ni < NF; ni++)
            acc[mi][ni][0] = acc[mi][ni][1] = acc[mi][ni][2] = acc[mi][ni][3] = 0.f;

    for (int k0 = 0; k0 < 128; k0 += KT) {
        #pragma unroll 2
        for (int i = tid; i < 128 * 8; i += 256) {
            int r = i >> 3, c = (i & 7) * 8;
            int gr = row0 + r;
            uint4 vh = make_uint4(0, 0, 0, 0), vl = make_uint4(0, 0, 0, 0);
            if (gr < NN) {
                vh = *(const uint4*)(Xhi + (size_t)gr * 128 + k0 + c);
                vl = *(const uint4*)(Xlo + (size_t)gr * 128 + k0 + c);
            }
            *(uint4*)(sXhi + r * XS + c) = vh;
            *(uint4*)(sXlo + r * XS + c) = vl;
        }
        #pragma unroll 2
        for (int i = tid; i < KT * WU4; i += 256) {
            int r = i / WU4, c = (i % WU4) * 8;
            *(uint4*)(sWhi + r * WS + c) = *(const uint4*)(Whi + (size_t)(k0 + r) * DOUT + c);
            *(uint4*)(sWlo + r * WS + c) = *(const uint4*)(Wlo + (size_t)(k0 + r) * DOUT + c);
        }
        __syncthreads();

        #pragma unroll
        for (int kk = 0; kk < KT; kk += 16) {
            uint32_t ahi[2][4], alo[2][4], bhi[NF][2], blo[NF][2];
            #pragma unroll
            for (int mi = 0; mi < 2; mi++) {
                int r = warpM * 32 + mi * 16 + (lane & 15);
                int c = kk + ((lane >> 4) << 3);
                ldsm_x4(ahi[mi], sptr(sXhi + r * XS + c));
                ldsm_x4(alo[mi], sptr(sXlo + r * XS + c));
            }
            #pragma unroll
            for (int ni = 0; ni < NF; ni++) {
                int r = kk + (lane & 15);
                int c = warpN * NW + ni * 8;
                ldsm_x2t(bhi[ni], sptr(sWhi + r * WS + c));
                ldsm_x2t(blo[ni], sptr(sWlo + r * WS + c));
            }
            #pragma unroll
            for (int mi = 0; mi < 2; mi++)
                #pragma unroll
                for (int ni = 0; ni < NF; ni++) {
                    mma_bf16(acc[mi][ni], ahi[mi], bhi[ni]);
                    mma_bf16(acc[mi][ni], ahi[mi], blo[ni]);
                    mma_bf16(acc[mi][ni], alo[mi], bhi[ni]);
                }
        }
        __syncthreads();
    }

    #pragma unroll
    for (int mi = 0; mi < 2; mi++) {
        int r0 = row0 + warpM * 32 + mi * 16 + (lane >> 2);
        int c0 = warpN * NW + (lane & 3) * 2;
        #pragma unroll
        for (int ni = 0; ni < NF; ni++) {
            int c = c0 + ni * 8;
            if (r0 < NN)
                *(float2*)(H + (size_t)r0 * DOUT + c) = make_float2(acc[mi][ni][0], acc[mi][ni][1]);
            if (r0 + 8 < NN)
                *(float2*)(H + (size_t)(r0 + 8) * DOUT + c) = make_float2(acc[mi][ni][2], acc[mi][ni][3]);
        }
    }
}

// ---------------- CSR aggregation, dim 128: warp per row, split output ---
// X' = relu( sum norm*H[src] + (1/deg)*H[d] + b ), written as bf16 hi/lo
__global__ void k_agg128(const float* __restrict__ H, const float* __restrict__ B) {
    int warp = (blockIdx.x * blockDim.x + threadIdx.x) >> 5;
    int lane = threadIdx.x & 31;
    if (warp >= NN) return;
    int d = warp;
    const float4* H4 = (const float4*)H;
    int p = g_rowptr[d], pe = g_rowptr[d + 1];
    float4 acc = make_float4(0.f, 0.f, 0.f, 0.f);
    for (; p + 4 <= pe; p += 4) {
        int s0 = g_csrc[p],     s1 = g_csrc[p + 1];
        int s2 = g_csrc[p + 2], s3 = g_csrc[p + 3];
        float n0 = g_cnorm[p],     n1 = g_cnorm[p + 1];
        float n2 = g_cnorm[p + 2], n3 = g_cnorm[p + 3];
        float4 v0 = H4[(size_t)s0 * 32 + lane];
        float4 v1 = H4[(size_t)s1 * 32 + lane];
        float4 v2 = H4[(size_t)s2 * 32 + lane];
        float4 v3 = H4[(size_t)s3 * 32 + lane];
        acc.x += n0 * v0.x + n1 * v1.x + n2 * v2.x + n3 * v3.x;
        acc.y += n0 * v0.y + n1 * v1.y + n2 * v2.y + n3 * v3.y;
        acc.z += n0 * v0.z + n1 * v1.z + n2 * v2.z + n3 * v3.z;
        acc.w += n0 * v0.w + n1 * v1.w + n2 * v2.w + n3 * v3.w;
    }
    for (; p < pe; p++) {
        int s = g_csrc[p]; float nm = g_cnorm[p];
        float4 v = H4[(size_t)s * 32 + lane];
        acc.x += nm * v.x; acc.y += nm * v.y; acc.z += nm * v.z; acc.w += nm * v.w;
    }
    float dv = g_dinv[d], sl = dv * dv;
    float4 hd = H4[(size_t)d * 32 + lane];
    float4 bv = ((const float4*)B)[lane];
    acc.x = fmaxf(acc.x + sl * hd.x + bv.x, 0.f);
    acc.y = fmaxf(acc.y + sl * hd.y + bv.y, 0.f);
    acc.z = fmaxf(acc.z + sl * hd.z + bv.z, 0.f);
    acc.w = fmaxf(acc.w + sl * hd.w + bv.w, 0.f);
    ushort4 hi4, lo4;
    hi4.x = f2bf(acc.x); lo4.x = f2bf(acc.x - bf2f(hi4.x));
    hi4.y = f2bf(acc.y); lo4.y = f2bf(acc.y - bf2f(hi4.y));
    hi4.z = f2bf(acc.z); lo4.z = f2bf(acc.z - bf2f(hi4.z));
    hi4.w = f2bf(acc.w); lo4.w = f2bf(acc.w - bf2f(hi4.w));
    *(ushort4*)((unsigned short*)g_Xhi + (size_t)d * 128 + lane * 4) = hi4;
    *(ushort4*)((unsigned short*)g_Xlo + (size_t)d * 128 + lane * 4) = lo4;
}

// ---------------- final agg (dim 64) fused with mean-pool scatter --------
__global__ void k_agg64_pool(const float* __restrict__ H, const float* __restrict__ B,
                             const void* __restrict__ batch) {
    int gt = blockIdx.x * blockDim.x + threadIdx.x;
    int d = gt >> 4;
    int c = gt & 15;
    if (d >= NN) return;
    const float4* H4 = (const float4*)H;
    int p = g_rowptr[d], pe = g_rowptr[d + 1];
    float4 acc = make_float4(0.f, 0.f, 0.f, 0.f);
    for (; p + 4 <= pe; p += 4) {
        int s0 = g_csrc[p],     s1 = g_csrc[p + 1];
        int s2 = g_csrc[p + 2], s3 = g_csrc[p + 3];
        float n0 = g_cnorm[p],     n1 = g_cnorm[p + 1];
        float n2 = g_cnorm[p + 2], n3 = g_cnorm[p + 3];
        float4 v0 = H4[(size_t)s0 * 16 + c];
        float4 v1 = H4[(size_t)s1 * 16 + c];
        float4 v2 = H4[(size_t)s2 * 16 + c];
        float4 v3 = H4[(size_t)s3 * 16 + c];
        acc.x += n0 * v0.x + n1 * v1.x + n2 * v2.x + n3 * v3.x;
        acc.y += n0 * v0.y + n1 * v1.y + n2 * v2.y + n3 * v3.y;
        acc.z += n0 * v0.z + n1 * v1.z + n2 * v2.z + n3 * v3.z;
        acc.w += n0 * v0.w + n1 * v1.w + n2 * v2.w + n3 * v3.w;
    }
    for (; p < pe; p++) {
        int s = g_csrc[p]; float nm = g_cnorm[p];
        float4 v = H4[(size_t)s * 16 + c];
        acc.x += nm * v.x; acc.y += nm * v.y; acc.z += nm * v.z; acc.w += nm * v.w;
    }
    float dv = g_dinv[d], sl = dv * dv;
    float4 hd = H4[(size_t)d * 16 + c];
    float4 bv = ((const float4*)B)[c];
    acc.x += sl * hd.x + bv.x;
    acc.y += sl * hd.y + bv.y;
    acc.z += sl * hd.z + bv.z;
    acc.w += sl * hd.w + bv.w;
    int g;
    if (g_b32) g = ((const int*)batch)[d];
    else       g = (int)((const long long*)batch)[d];
    red_add_v4(&g_pool[g * 64 + c * 4], acc.x, acc.y, acc.z, acc.w);
    if (c == 0) atomicAdd(&g_cnt[g], 1.0f);
}

// ---------------- final MLP ----------------
__global__ void k_mlp(const float* __restrict__ Wl1, const float* __restrict__ bl1,
                      const float* __restrict__ Wl2, const float* __restrict__ bl2,
                      float* __restrict__ out) {
    __shared__ float mean[64];
    __shared__ float hid[32];
    int g = blockIdx.x;
    int t = threadIdx.x;
    float cnt = fmaxf(g_cnt[g], 1.0f);
    mean[t] = g_pool[g * 64 + t] / cnt;
    __syncthreads();
    if (t < 32) {
        float s = bl1[t];
        #pragma unroll 8
        for (int k = 0; k < 64; k++) s += mean[k] * Wl1[k * 32 + t];
        hid[t] = fmaxf(s, 0.0f);
    }
    __syncthreads();
    if (t < 9) {
        float s = bl2[t];
        #pragma unroll 8
        for (int k = 0; k < 32; k++) s += hid[k] * Wl2[k * 9 + t];
        out[g * 9 + t] = s;
    }
}

// ---------------- launch ----------------
extern "C" void kernel_launch(void* const* d_in, const int* in_sizes, int n_in,
                              void* d_out, int out_size) {
    const float* x     = (const float*)d_in[0];
    const void*  ei    = d_in[1];
    const void*  batch = d_in[2];
    const float* W1 = (const float*)d_in[3];  const float* b1 = (const float*)d_in[4];
    const float* W2 = (const float*)d_in[5];  const float* b2 = (const float*)d_in[6];
    const float* W3 = (const float*)d_in[7];  const float* b3 = (const float*)d_in[8];
    const float* W4 = (const float*)d_in[9];  const float* b4 = (const float*)d_in[10];
    const float* Wl1 = (const float*)d_in[11]; const float* bl1 = (const float*)d_in[12];
    const float* Wl2 = (const float*)d_in[13]; const float* bl2 = (const float*)d_in[14];
    float* out = (float*)d_out;

    float *buf1, *bufA;
    __nv_bfloat16 *xhi, *xlo, *w2hi, *w2lo, *w3hi, *w3lo, *w4hi, *w4lo;
    cudaGetSymbolAddress((void**)&buf1, g_buf1);
    cudaGetSymbolAddress((void**)&bufA, g_bufA);
    cudaGetSymbolAddress((void**)&xhi, g_Xhi);
    cudaGetSymbolAddress((void**)&xlo, g_Xlo);
    cudaGetSymbolAddress((void**)&w2hi, g_W2hi); cudaGetSymbolAddress((void**)&w2lo, g_W2lo);
    cudaGetSymbolAddress((void**)&w3hi, g_W3hi); cudaGetSymbolAddress((void**)&w3lo, g_W3lo);
    cudaGetSymbolAddress((void**)&w4hi, g_W4hi); cudaGetSymbolAddress((void**)&w4lo, g_W4lo);

    const int smem128 = (2 * 128 * 72 + 2 * 64 * 136) * 2;   // 71680
    const int smem64  = (2 * 128 * 72 + 2 * 64 * 72) * 2;    // 55296
    cudaFuncSetAttribute((const void*)k_gemm_tc<128>,
                         cudaFuncAttributeMaxDynamicSharedMemorySize, smem128);
    cudaFuncSetAttribute((const void*)k_gemm_tc<64>,
                         cudaFuncAttributeMaxDynamicSharedMemorySize, smem64);

    // preprocessing
    k_detect<<<1, 256>>>((const unsigned*)ei, (const unsigned*)batch);
    k_zero<<<(NN + 255) / 256, 256>>>();
    k_deg<<<NE / 256, 256>>>(ei);
    k_scan1<<<NB_SCAN, 512>>>();
    k_scan2<<<1, 256>>>();
    k_scan3<<<(NN + 255) / 256, 256>>>();
    k_build<<<NE / 256, 256>>>();
    k_wsplit<<<160, 256>>>(W2, W3, W4);

    const int GTC = (NN + 127) / 128;   // 782

    // layer 1: A = Â x (dim 3), X2 = relu(A @ W1 + b1) -> hi/lo
    k_agg3<<<(NN + 255) / 256, 256>>>(x);
    k_gemm3<<<NN / 32, dim3(32, 4)>>>(bufA, W1, b1);

    // layer 2
    k_gemm_tc<128><<<GTC, 256, smem128>>>(xhi, xlo, w2hi, w2lo, buf1);
    k_agg128<<<12500, 256>>>(buf1, b2);
    // layer 3
    k_gemm_tc<128><<<GTC, 256, smem128>>>(xhi, xlo, w3hi, w3lo, buf1);
    k_agg128<<<12500, 256>>>(buf1, b3);
    // layer 4
    k_gemm_tc<64><<<GTC, 256, smem64>>>(xhi, xlo, w4hi, w4lo, buf1);
    k_agg64_pool<<<(NN * 16) / 256, 256>>>(buf1, b4, batch);

    k_mlp<<<NG, 64>>>(Wl1, bl1, Wl2, bl2, out);
}

// round 5
// speedup vs baseline: 3.3226x; 1.0688x over previous
#include <cuda_runtime.h>
#include <cuda_bf16.h>
#include <cuda_fp16.h>
#include <cstdint>
#include <math.h>

#define NN 100000
#define NE 1600000
#define NG 512
#define NB_SCAN 196   // ceil(NN/512)

// ---------------- device scratch (static, no allocations) ----------------
__device__ __align__(16) __half g_H[NN * 128];            // GEMM out (fp16)
__device__ __align__(16) __nv_bfloat16 g_Xhi[NN * 128];   // activation hi
__device__ __align__(16) __nv_bfloat16 g_Xlo[NN * 128];   // activation lo
__device__ __align__(16) float g_bufA[NN * 3];
__device__ __align__(16) __nv_bfloat16 g_W2hi[16384], g_W2lo[16384];
__device__ __align__(16) __nv_bfloat16 g_W3hi[16384], g_W3lo[16384];
__device__ __align__(16) __nv_bfloat16 g_W4hi[8192],  g_W4lo[8192];
__device__ int   g_ideg[NN];
__device__ float g_dinv[NN];
__device__ int   g_csrc[NE];
__device__ float g_cnorm[NE];
__device__ int   g_rowptr[NN + 1];
__device__ int   g_cur[NN];
__device__ int   g_bsum[256];
__device__ __align__(16) float g_pool[NG * 64];
__device__ float g_cnt[NG];
__device__ int   g_e32;
__device__ int   g_b32;

// ---------------- helpers ----------------
__device__ __forceinline__ void red_add_v4(float* p, float a, float b, float c, float d) {
    asm volatile("red.global.add.v4.f32 [%0], {%1,%2,%3,%4};"
                 :: "l"(p), "f"(a), "f"(b), "f"(c), "f"(d) : "memory");
}
__device__ __forceinline__ unsigned short f2bf(float f) {
    __nv_bfloat16 b = __float2bfloat16(f);
    return *(unsigned short*)&b;
}
__device__ __forceinline__ float bf2f(unsigned short u) {
    __nv_bfloat16 b = *(__nv_bfloat16*)&u;
    return __bfloat162float(b);
}
__device__ __forceinline__ uint32_t sptr(const void* p) {
    return (uint32_t)__cvta_generic_to_shared(p);
}
__device__ __forceinline__ void ldsm_x4(uint32_t (&r)[4], uint32_t a) {
    asm volatile("ldmatrix.sync.aligned.m8n8.x4.shared.b16 {%0,%1,%2,%3}, [%4];"
                 : "=r"(r[0]), "=r"(r[1]), "=r"(r[2]), "=r"(r[3]) : "r"(a));
}
__device__ __forceinline__ void ldsm_x2t(uint32_t (&r)[2], uint32_t a) {
    asm volatile("ldmatrix.sync.aligned.m8n8.x2.trans.shared.b16 {%0,%1}, [%2];"
                 : "=r"(r[0]), "=r"(r[1]) : "r"(a));
}
__device__ __forceinline__ void mma_bf16(float (&d)[4], const uint32_t (&a)[4],
                                         const uint32_t (&b)[2]) {
    asm volatile("mma.sync.aligned.m16n8k16.row.col.f32.bf16.bf16.f32 "
                 "{%0,%1,%2,%3}, {%4,%5,%6,%7}, {%8,%9}, {%0,%1,%2,%3};"
                 : "+f"(d[0]), "+f"(d[1]), "+f"(d[2]), "+f"(d[3])
                 : "r"(a[0]), "r"(a[1]), "r"(a[2]), "r"(a[3]), "r"(b[0]), "r"(b[1]));
}
// unpack uint2 (4 halves) -> accumulate with weight
__device__ __forceinline__ void acc_h4(float4& acc, uint2 u, float n) {
    float2 a = __half22float2(*(__half2*)&u.x);
    float2 b = __half22float2(*(__half2*)&u.y);
    acc.x += n * a.x; acc.y += n * a.y; acc.z += n * b.x; acc.w += n * b.y;
}

// ---------------- dtype detection (int32 vs int64 index arrays) ----------
__global__ void k_detect(const unsigned* __restrict__ e, const unsigned* __restrict__ b) {
    __shared__ unsigned se[256], sb[256];
    int t = threadIdx.x;
    unsigned ae = 0, ab = 0;
    const int SE = (2 * NE) / 4096;
    const int SB = NN / 4096;
    for (int i = t; i < 4096; i += 256) {
        ae |= e[(i * SE) | 1];
        ab |= b[(i * SB) | 1];
    }
    se[t] = ae; sb[t] = ab;
    __syncthreads();
    for (int s = 128; s; s >>= 1) {
        if (t < s) { se[t] |= se[t + s]; sb[t] |= sb[t + s]; }
        __syncthreads();
    }
    if (t == 0) { g_e32 = (se[0] != 0); g_b32 = (sb[0] != 0); }
}

__global__ void k_zero() {
    int i = blockIdx.x * blockDim.x + threadIdx.x;
    if (i < NN) g_ideg[i] = 0;
    if (i < NG * 64) g_pool[i] = 0.0f;
    if (i < NG) g_cnt[i] = 0.0f;
}

// degree count (reads edge_index directly)
__global__ void k_deg(const void* __restrict__ ei) {
    int e = blockIdx.x * blockDim.x + threadIdx.x;
    if (e >= NE) return;
    int d;
    if (g_e32) d = ((const int*)ei)[NE + e];
    else       d = (int)((const long long*)ei)[NE + e];
    atomicAdd(&g_ideg[d], 1);
}

// ---------------- 2-level exclusive scan of degrees -> rowptr ------------
__global__ void k_scan1() {
    __shared__ int sm[512];
    int t = threadIdx.x;
    int i = blockIdx.x * 512 + t;
    int v = (i < NN) ? g_ideg[i] : 0;
    sm[t] = v;
    __syncthreads();
    for (int off = 1; off < 512; off <<= 1) {
        int x = 0;
        if (t >= off) x = sm[t - off];
        __syncthreads();
        if (t >= off) sm[t] += x;
        __syncthreads();
    }
    if (i < NN) g_rowptr[i] = sm[t] - v;
    if (t == 511) g_bsum[blockIdx.x] = sm[511];
}

__global__ void k_scan2() {
    __shared__ int sm[256];
    int t = threadIdx.x;
    int v = (t < NB_SCAN) ? g_bsum[t] : 0;
    sm[t] = v;
    __syncthreads();
    for (int off = 1; off < 256; off <<= 1) {
        int x = 0;
        if (t >= off) x = sm[t - off];
        __syncthreads();
        if (t >= off) sm[t] += x;
        __syncthreads();
    }
    if (t < NB_SCAN) g_bsum[t] = sm[t] - v;
}

__global__ void k_scan3() {
    int i = blockIdx.x * blockDim.x + threadIdx.x;
    if (i < NN) {
        int r = g_rowptr[i] + g_bsum[i >> 9];
        g_rowptr[i] = r;
        g_cur[i] = r;
        g_dinv[i] = rsqrtf((float)g_ideg[i] + 1.0f);
    }
    if (i == 0) g_rowptr[NN] = NE;
}

// scatter edges into CSR (sorted by dst); reads edge_index directly
__global__ void k_build(const void* __restrict__ ei) {
    int e = blockIdx.x * blockDim.x + threadIdx.x;
    if (e >= NE) return;
    int s, d;
    if (g_e32) {
        const int* p = (const int*)ei;
        s = p[e]; d = p[NE + e];
    } else {
        const long long* p = (const long long*)ei;
        s = (int)p[e]; d = (int)p[NE + e];
    }
    int pos = atomicAdd(&g_cur[d], 1);
    g_csrc[pos] = s;
    g_cnorm[pos] = g_dinv[s] * g_dinv[d];
}

// ---------------- W split: f32 -> bf16 hi/lo ----------------
__global__ void k_wsplit(const float* __restrict__ W2, const float* __restrict__ W3,
                         const float* __restrict__ W4) {
    int i = blockIdx.x * blockDim.x + threadIdx.x;
    float v; __nv_bfloat16* hi; __nv_bfloat16* lo; int j;
    if (i < 16384)      { j = i;         v = W2[j]; hi = g_W2hi; lo = g_W2lo; }
    else if (i < 32768) { j = i - 16384; v = W3[j]; hi = g_W3hi; lo = g_W3lo; }
    else if (i < 40960) { j = i - 32768; v = W4[j]; hi = g_W4hi; lo = g_W4lo; }
    else return;
    unsigned short h = f2bf(v);
    hi[j] = *(__nv_bfloat16*)&h;
    unsigned short l = f2bf(v - bf2f(h));
    lo[j] = *(__nv_bfloat16*)&l;
}

// ---------------- layer-1 input aggregation: A = Â x (dim 3) -------------
__global__ void k_agg3(const float* __restrict__ x) {
    int d = blockIdx.x * blockDim.x + threadIdx.x;
    if (d >= NN) return;
    int p = g_rowptr[d], pe = g_rowptr[d + 1];
    float a0 = 0.f, a1 = 0.f, a2 = 0.f;
    for (; p + 2 <= pe; p += 2) {
        int s0 = g_csrc[p], s1 = g_csrc[p + 1];
        float n0 = g_cnorm[p], n1 = g_cnorm[p + 1];
        a0 += n0 * x[s0 * 3]     + n1 * x[s1 * 3];
        a1 += n0 * x[s0 * 3 + 1] + n1 * x[s1 * 3 + 1];
        a2 += n0 * x[s0 * 3 + 2] + n1 * x[s1 * 3 + 2];
    }
    for (; p < pe; p++) {
        int s = g_csrc[p]; float nm = g_cnorm[p];
        a0 += nm * x[s * 3]; a1 += nm * x[s * 3 + 1]; a2 += nm * x[s * 3 + 2];
    }
    float dv = g_dinv[d], sl = dv * dv;
    g_bufA[d * 3 + 0] = a0 + sl * x[d * 3 + 0];
    g_bufA[d * 3 + 1] = a1 + sl * x[d * 3 + 1];
    g_bufA[d * 3 + 2] = a2 + sl * x[d * 3 + 2];
}

// ---------------- layer-1 GEMM: X2 = relu(A @ W1 + b1), split output -----
__global__ void k_gemm3(const float* __restrict__ X, const float* __restrict__ W,
                        const float* __restrict__ B) {
    __shared__ float Ws[3 * 128];
    __shared__ float xs[32 * 3];
    const int tx = threadIdx.x;
    const int ty = threadIdx.y;
    const int tid = ty * 32 + tx;
    const int row0 = blockIdx.x * 32;
    for (int i = tid; i < 3 * 128; i += 128) Ws[i] = W[i];
    if (tid < 96) xs[tid] = X[(size_t)row0 * 3 + tid];
    __syncthreads();

    float4 wv[3];
    #pragma unroll
    for (int k = 0; k < 3; k++) wv[k] = ((const float4*)Ws)[k * 32 + tx];
    float4 bv = ((const float4*)B)[tx];

    #pragma unroll
    for (int r = 0; r < 8; r++) {
        int row = row0 + ty * 8 + r;
        float x0 = xs[(ty * 8 + r) * 3], x1 = xs[(ty * 8 + r) * 3 + 1],
              x2 = xs[(ty * 8 + r) * 3 + 2];
        float4 h;
        h.x = fmaxf(x0 * wv[0].x + x1 * wv[1].x + x2 * wv[2].x + bv.x, 0.f);
        h.y = fmaxf(x0 * wv[0].y + x1 * wv[1].y + x2 * wv[2].y + bv.y, 0.f);
        h.z = fmaxf(x0 * wv[0].z + x1 * wv[1].z + x2 * wv[2].z + bv.z, 0.f);
        h.w = fmaxf(x0 * wv[0].w + x1 * wv[1].w + x2 * wv[2].w + bv.w, 0.f);
        ushort4 hi4, lo4;
        hi4.x = f2bf(h.x); lo4.x = f2bf(h.x - bf2f(hi4.x));
        hi4.y = f2bf(h.y); lo4.y = f2bf(h.y - bf2f(hi4.y));
        hi4.z = f2bf(h.z); lo4.z = f2bf(h.z - bf2f(hi4.z));
        hi4.w = f2bf(h.w); lo4.w = f2bf(h.w - bf2f(hi4.w));
        *(ushort4*)((unsigned short*)g_Xhi + (size_t)row * 128 + tx * 4) = hi4;
        *(ushort4*)((unsigned short*)g_Xlo + (size_t)row * 128 + tx * 4) = lo4;
    }
}

// ---------------- tensor-core GEMM: H = (Xhi+Xlo)@(Whi+Wlo), fp16 out ----
template<int DOUT>
__global__ __launch_bounds__(256) void k_gemm_tc(
    const __nv_bfloat16* __restrict__ Xhi, const __nv_bfloat16* __restrict__ Xlo,
    const __nv_bfloat16* __restrict__ Whi, const __nv_bfloat16* __restrict__ Wlo,
    __half* __restrict__ H) {
    constexpr int KT = 64;
    constexpr int XS = 72;
    constexpr int WS = DOUT + 8;
    constexpr int NW = DOUT / 2;
    constexpr int NF = NW / 8;
    constexpr int WU4 = DOUT / 8;
    extern __shared__ __nv_bfloat16 smem[];
    __nv_bfloat16* sXhi = smem;
    __nv_bfloat16* sXlo = sXhi + 128 * XS;
    __nv_bfloat16* sWhi = sXlo + 128 * XS;
    __nv_bfloat16* sWlo = sWhi + KT * WS;

    const int tid = threadIdx.x;
    const int wid = tid >> 5;
    const int lane = tid & 31;
    const int warpM = wid & 3;
    const int warpN = wid >> 2;
    const int row0 = blockIdx.x * 128;

    float acc[2][NF][4];
    #pragma unroll
    for (int mi = 0; mi < 2; mi++)
        #pragma unroll
        for (int ni = 0; ni < NF; ni++)
            acc[mi][ni][0] = acc[mi][ni][1] = acc[mi][ni][2] = acc[mi][ni][3] = 0.f;

    for (int k0 = 0; k0 < 128; k0 += KT) {
        #pragma unroll 2
        for (int i = tid; i < 128 * 8; i += 256) {
            int r = i >> 3, c = (i & 7) * 8;
            int gr = row0 + r;
            uint4 vh = make_uint4(0, 0, 0, 0), vl = make_uint4(0, 0, 0, 0);
            if (gr < NN) {
                vh = *(const uint4*)(Xhi + (size_t)gr * 128 + k0 + c);
                vl = *(const uint4*)(Xlo + (size_t)gr * 128 + k0 + c);
            }
            *(uint4*)(sXhi + r * XS + c) = vh;
            *(uint4*)(sXlo + r * XS + c) = vl;
        }
        #pragma unroll 2
        for (int i = tid; i < KT * WU4; i += 256) {
            int r = i / WU4, c = (i % WU4) * 8;
            *(uint4*)(sWhi + r * WS + c) = *(const uint4*)(Whi + (size_t)(k0 + r) * DOUT + c);
            *(uint4*)(sWlo + r * WS + c) = *(const uint4*)(Wlo + (size_t)(k0 + r) * DOUT + c);
        }
        __syncthreads();

        #pragma unroll
        for (int kk = 0; kk < KT; kk += 16) {
            uint32_t ahi[2][4], alo[2][4], bhi[NF][2], blo[NF][2];
            #pragma unroll
            for (int mi = 0; mi < 2; mi++) {
                int r = warpM * 32 + mi * 16 + (lane & 15);
                int c = kk + ((lane >> 4) << 3);
                ldsm_x4(ahi[mi], sptr(sXhi + r * XS + c));
                ldsm_x4(alo[mi], sptr(sXlo + r * XS + c));
            }
            #pragma unroll
            for (int ni = 0; ni < NF; ni++) {
                int r = kk + (lane & 15);
                int c = warpN * NW + ni * 8;
                ldsm_x2t(bhi[ni], sptr(sWhi + r * WS + c));
                ldsm_x2t(blo[ni], sptr(sWlo + r * WS + c));
            }
            #pragma unroll
            for (int mi = 0; mi < 2; mi++)
                #pragma unroll
                for (int ni = 0; ni < NF; ni++) {
                    mma_bf16(acc[mi][ni], ahi[mi], bhi[ni]);
                    mma_bf16(acc[mi][ni], ahi[mi], blo[ni]);
                    mma_bf16(acc[mi][ni], alo[mi], bhi[ni]);
                }
        }
        __syncthreads();
    }

    #pragma unroll
    for (int mi = 0; mi < 2; mi++) {
        int r0 = row0 + warpM * 32 + mi * 16 + (lane >> 2);
        int c0 = warpN * NW + (lane & 3) * 2;
        #pragma unroll
        for (int ni = 0; ni < NF; ni++) {
            int c = c0 + ni * 8;
            if (r0 < NN) {
                __half2 h = __floats2half2_rn(acc[mi][ni][0], acc[mi][ni][1]);
                *(__half2*)(H + (size_t)r0 * DOUT + c) = h;
            }
            if (r0 + 8 < NN) {
                __half2 h = __floats2half2_rn(acc[mi][ni][2], acc[mi][ni][3]);
                *(__half2*)(H + (size_t)(r0 + 8) * DOUT + c) = h;
            }
        }
    }
}

// ---------------- CSR aggregation, dim 128 (fp16 gather, f32 accum) ------
// X' = relu( sum norm*H[src] + (1/deg)*H[d] + b ) -> bf16 hi/lo split
__global__ void k_agg128(const __half* __restrict__ H, const float* __restrict__ B) {
    int warp = (blockIdx.x * blockDim.x + threadIdx.x) >> 5;
    int lane = threadIdx.x & 31;
    if (warp >= NN) return;
    int d = warp;
    const uint2* H2 = (const uint2*)H;   // 4 halves per lane, 32 lanes = 128
    int p = g_rowptr[d], pe = g_rowptr[d + 1];
    float4 acc = make_float4(0.f, 0.f, 0.f, 0.f);
    for (; p + 4 <= pe; p += 4) {
        int s0 = g_csrc[p],     s1 = g_csrc[p + 1];
        int s2 = g_csrc[p + 2], s3 = g_csrc[p + 3];
        float n0 = g_cnorm[p],     n1 = g_cnorm[p + 1];
        float n2 = g_cnorm[p + 2], n3 = g_cnorm[p + 3];
        uint2 u0 = H2[(size_t)s0 * 32 + lane];
        uint2 u1 = H2[(size_t)s1 * 32 + lane];
        uint2 u2 = H2[(size_t)s2 * 32 + lane];
        uint2 u3 = H2[(size_t)s3 * 32 + lane];
        acc_h4(acc, u0, n0); acc_h4(acc, u1, n1);
        acc_h4(acc, u2, n2); acc_h4(acc, u3, n3);
    }
    for (; p < pe; p++) {
        int s = g_csrc[p];
        acc_h4(acc, H2[(size_t)s * 32 + lane], g_cnorm[p]);
    }
    float dv = g_dinv[d], sl = dv * dv;
    acc_h4(acc, H2[(size_t)d * 32 + lane], sl);
    float4 bv = ((const float4*)B)[lane];
    acc.x = fmaxf(acc.x + bv.x, 0.f);
    acc.y = fmaxf(acc.y + bv.y, 0.f);
    acc.z = fmaxf(acc.z + bv.z, 0.f);
    acc.w = fmaxf(acc.w + bv.w, 0.f);
    ushort4 hi4, lo4;
    hi4.x = f2bf(acc.x); lo4.x = f2bf(acc.x - bf2f(hi4.x));
    hi4.y = f2bf(acc.y); lo4.y = f2bf(acc.y - bf2f(hi4.y));
    hi4.z = f2bf(acc.z); lo4.z = f2bf(acc.z - bf2f(hi4.z));
    hi4.w = f2bf(acc.w); lo4.w = f2bf(acc.w - bf2f(hi4.w));
    *(ushort4*)((unsigned short*)g_Xhi + (size_t)d * 128 + lane * 4) = hi4;
    *(ushort4*)((unsigned short*)g_Xlo + (size_t)d * 128 + lane * 4) = lo4;
}

// ---------------- final agg (dim 64, fp16 gather) + mean-pool scatter ----
__global__ void k_agg64_pool(const __half* __restrict__ H, const float* __restrict__ B,
                             const void* __restrict__ batch) {
    int gt = blockIdx.x * blockDim.x + threadIdx.x;
    int d = gt >> 4;            // 16 lanes of 4 halves per row
    int c = gt & 15;
    if (d >= NN) return;
    const uint2* H2 = (const uint2*)H;
    int p = g_rowptr[d], pe = g_rowptr[d + 1];
    float4 acc = make_float4(0.f, 0.f, 0.f, 0.f);
    for (; p + 4 <= pe; p += 4) {
        int s0 = g_csrc[p],     s1 = g_csrc[p + 1];
        int s2 = g_csrc[p + 2], s3 = g_csrc[p + 3];
        float n0 = g_cnorm[p],     n1 = g_cnorm[p + 1];
        float n2 = g_cnorm[p + 2], n3 = g_cnorm[p + 3];
        acc_h4(acc, H2[(size_t)s0 * 16 + c], n0);
        acc_h4(acc, H2[(size_t)s1 * 16 + c], n1);
        acc_h4(acc, H2[(size_t)s2 * 16 + c], n2);
        acc_h4(acc, H2[(size_t)s3 * 16 + c], n3);
    }
    for (; p < pe; p++) {
        acc_h4(acc, H2[(size_t)g_csrc[p] * 16 + c], g_cnorm[p]);
    }
    float dv = g_dinv[d], sl = dv * dv;
    acc_h4(acc, H2[(size_t)d * 16 + c], sl);
    float4 bv = ((const float4*)B)[c];
    acc.x += bv.x; acc.y += bv.y; acc.z += bv.z; acc.w += bv.w;
    int g;
    if (g_b32) g = ((const int*)batch)[d];
    else       g = (int)((const long long*)batch)[d];
    red_add_v4(&g_pool[g * 64 + c * 4], acc.x, acc.y, acc.z, acc.w);
    if (c == 0) atomicAdd(&g_cnt[g], 1.0f);
}

// ---------------- final MLP ----------------
__global__ void k_mlp(const float* __restrict__ Wl1, const float* __restrict__ bl1,
                      const float* __restrict__ Wl2, const float* __restrict__ bl2,
                      float* __restrict__ out) {
    __shared__ float mean[64];
    __shared__ float hid[32];
    int g = blockIdx.x;
    int t = threadIdx.x;
    float cnt = fmaxf(g_cnt[g], 1.0f);
    mean[t] = g_pool[g * 64 + t] / cnt;
    __syncthreads();
    if (t < 32) {
        float s = bl1[t];
        #pragma unroll 8
        for (int k = 0; k < 64; k++) s += mean[k] * Wl1[k * 32 + t];
        hid[t] = fmaxf(s, 0.0f);
    }
    __syncthreads();
    if (t < 9) {
        float s = bl2[t];
        #pragma unroll 8
        for (int k = 0; k < 32; k++) s += hid[k] * Wl2[k * 9 + t];
        out[g * 9 + t] = s;
    }
}

// ---------------- launch ----------------
extern "C" void kernel_launch(void* const* d_in, const int* in_sizes, int n_in,
                              void* d_out, int out_size) {
    const float* x     = (const float*)d_in[0];
    const void*  ei    = d_in[1];
    const void*  batch = d_in[2];
    const float* W1 = (const float*)d_in[3];  const float* b1 = (const float*)d_in[4];
    const float* W2 = (const float*)d_in[5];  const float* b2 = (const float*)d_in[6];
    const float* W3 = (const float*)d_in[7];  const float* b3 = (const float*)d_in[8];
    const float* W4 = (const float*)d_in[9];  const float* b4 = (const float*)d_in[10];
    const float* Wl1 = (const float*)d_in[11]; const float* bl1 = (const float*)d_in[12];
    const float* Wl2 = (const float*)d_in[13]; const float* bl2 = (const float*)d_in[14];
    float* out = (float*)d_out;

    float *bufA;
    __half* bufH;
    __nv_bfloat16 *xhi, *xlo, *w2hi, *w2lo, *w3hi, *w3lo, *w4hi, *w4lo;
    cudaGetSymbolAddress((void**)&bufH, g_H);
    cudaGetSymbolAddress((void**)&bufA, g_bufA);
    cudaGetSymbolAddress((void**)&xhi, g_Xhi);
    cudaGetSymbolAddress((void**)&xlo, g_Xlo);
    cudaGetSymbolAddress((void**)&w2hi, g_W2hi); cudaGetSymbolAddress((void**)&w2lo, g_W2lo);
    cudaGetSymbolAddress((void**)&w3hi, g_W3hi); cudaGetSymbolAddress((void**)&w3lo, g_W3lo);
    cudaGetSymbolAddress((void**)&w4hi, g_W4hi); cudaGetSymbolAddress((void**)&w4lo, g_W4lo);

    const int smem128 = (2 * 128 * 72 + 2 * 64 * 136) * 2;   // 71680
    const int smem64  = (2 * 128 * 72 + 2 * 64 * 72) * 2;    // 55296
    cudaFuncSetAttribute((const void*)k_gemm_tc<128>,
                         cudaFuncAttributeMaxDynamicSharedMemorySize, smem128);
    cudaFuncSetAttribute((const void*)k_gemm_tc<64>,
                         cudaFuncAttributeMaxDynamicSharedMemorySize, smem64);

    // preprocessing
    k_detect<<<1, 256>>>((const unsigned*)ei, (const unsigned*)batch);
    k_zero<<<(NN + 255) / 256, 256>>>();
    k_deg<<<NE / 256, 256>>>(ei);
    k_scan1<<<NB_SCAN, 512>>>();
    k_scan2<<<1, 256>>>();
    k_scan3<<<(NN + 255) / 256, 256>>>();
    k_build<<<NE / 256, 256>>>(ei);
    k_wsplit<<<160, 256>>>(W2, W3, W4);

    const int GTC = (NN + 127) / 128;   // 782

    // layer 1: A = Â x (dim 3), X2 = relu(A @ W1 + b1) -> hi/lo
    k_agg3<<<(NN + 255) / 256, 256>>>(x);
    k_gemm3<<<NN / 32, dim3(32, 4)>>>(bufA, W1, b1);

    // layer 2
    k_gemm_tc<128><<<GTC, 256, smem128>>>(xhi, xlo, w2hi, w2lo, bufH);
    k_agg128<<<12500, 256>>>(bufH, b2);
    // layer 3
    k_gemm_tc<128><<<GTC, 256, smem128>>>(xhi, xlo, w3hi, w3lo, bufH);
    k_agg128<<<12500, 256>>>(bufH, b3);
    // layer 4
    k_gemm_tc<64><<<GTC, 256, smem64>>>(xhi, xlo, w4hi, w4lo, bufH);
    k_agg64_pool<<<(NN * 16) / 256, 256>>>(bufH, b4, batch);

    k_mlp<<<NG, 64>>>(Wl1, bl1, Wl2, bl2, out);
}

// round 6
// speedup vs baseline: 3.8690x; 1.1645x over previous
#include <cuda_runtime.h>
#include <cuda_fp16.h>
#include <cstdint>
#include <math.h>

#define NN 100000
#define NE 1600000
#define NG 512
#define NB_SCAN 196   // ceil(NN/512)

// ---------------- device scratch (static, no allocations) ----------------
__device__ __align__(16) __half g_H[NN * 128];   // GEMM out (fp16)
__device__ __align__(16) __half g_X[NN * 128];   // activations (fp16)
__device__ __align__(16) float g_bufA[NN * 3];
__device__ __align__(16) __half g_W2[16384], g_W3[16384], g_W4[8192];
__device__ int   g_ideg[NN];
__device__ float g_dinv[NN];
__device__ int   g_csrc[NE];
__device__ float g_cnorm[NE];
__device__ int   g_rowptr[NN + 1];
__device__ int   g_cur[NN];
__device__ int   g_bsum[256];
__device__ __align__(16) float g_pool[NG * 64];
__device__ float g_cnt[NG];
__device__ int   g_e32;
__device__ int   g_b32;

// ---------------- helpers ----------------
__device__ __forceinline__ void red_add_v4(float* p, float a, float b, float c, float d) {
    asm volatile("red.global.add.v4.f32 [%0], {%1,%2,%3,%4};"
                 :: "l"(p), "f"(a), "f"(b), "f"(c), "f"(d) : "memory");
}
__device__ __forceinline__ uint32_t sptr(const void* p) {
    return (uint32_t)__cvta_generic_to_shared(p);
}
__device__ __forceinline__ void ldsm_x4(uint32_t (&r)[4], uint32_t a) {
    asm volatile("ldmatrix.sync.aligned.m8n8.x4.shared.b16 {%0,%1,%2,%3}, [%4];"
                 : "=r"(r[0]), "=r"(r[1]), "=r"(r[2]), "=r"(r[3]) : "r"(a));
}
__device__ __forceinline__ void ldsm_x2t(uint32_t (&r)[2], uint32_t a) {
    asm volatile("ldmatrix.sync.aligned.m8n8.x2.trans.shared.b16 {%0,%1}, [%2];"
                 : "=r"(r[0]), "=r"(r[1]) : "r"(a));
}
__device__ __forceinline__ void mma_f16(float (&d)[4], const uint32_t (&a)[4],
                                        const uint32_t (&b)[2]) {
    asm volatile("mma.sync.aligned.m16n8k16.row.col.f32.f16.f16.f32 "
                 "{%0,%1,%2,%3}, {%4,%5,%6,%7}, {%8,%9}, {%0,%1,%2,%3};"
                 : "+f"(d[0]), "+f"(d[1]), "+f"(d[2]), "+f"(d[3])
                 : "r"(a[0]), "r"(a[1]), "r"(a[2]), "r"(a[3]), "r"(b[0]), "r"(b[1]));
}
// unpack uint2 (4 halves) -> accumulate with weight
__device__ __forceinline__ void acc_h4(float4& acc, uint2 u, float n) {
    float2 a = __half22float2(*(__half2*)&u.x);
    float2 b = __half22float2(*(__half2*)&u.y);
    acc.x += n * a.x; acc.y += n * a.y; acc.z += n * b.x; acc.w += n * b.y;
}

// ---------------- dtype detection (int32 vs int64 index arrays) ----------
__global__ void k_detect(const unsigned* __restrict__ e, const unsigned* __restrict__ b) {
    __shared__ unsigned se[256], sb[256];
    int t = threadIdx.x;
    unsigned ae = 0, ab = 0;
    const int SE = (2 * NE) / 4096;
    const int SB = NN / 4096;
    for (int i = t; i < 4096; i += 256) {
        ae |= e[(i * SE) | 1];
        ab |= b[(i * SB) | 1];
    }
    se[t] = ae; sb[t] = ab;
    __syncthreads();
    for (int s = 128; s; s >>= 1) {
        if (t < s) { se[t] |= se[t + s]; sb[t] |= sb[t + s]; }
        __syncthreads();
    }
    if (t == 0) { g_e32 = (se[0] != 0); g_b32 = (sb[0] != 0); }
}

__global__ void k_zero() {
    int i = blockIdx.x * blockDim.x + threadIdx.x;
    if (i < NN) g_ideg[i] = 0;
    if (i < NG * 64) g_pool[i] = 0.0f;
    if (i < NG) g_cnt[i] = 0.0f;
}

__global__ void k_deg(const void* __restrict__ ei) {
    int e = blockIdx.x * blockDim.x + threadIdx.x;
    if (e >= NE) return;
    int d;
    if (g_e32) d = ((const int*)ei)[NE + e];
    else       d = (int)((const long long*)ei)[NE + e];
    atomicAdd(&g_ideg[d], 1);
}

// ---------------- 2-level exclusive scan of degrees -> rowptr ------------
__global__ void k_scan1() {
    __shared__ int sm[512];
    int t = threadIdx.x;
    int i = blockIdx.x * 512 + t;
    int v = (i < NN) ? g_ideg[i] : 0;
    sm[t] = v;
    __syncthreads();
    for (int off = 1; off < 512; off <<= 1) {
        int x = 0;
        if (t >= off) x = sm[t - off];
        __syncthreads();
        if (t >= off) sm[t] += x;
        __syncthreads();
    }
    if (i < NN) g_rowptr[i] = sm[t] - v;
    if (t == 511) g_bsum[blockIdx.x] = sm[511];
}

__global__ void k_scan2() {
    __shared__ int sm[256];
    int t = threadIdx.x;
    int v = (t < NB_SCAN) ? g_bsum[t] : 0;
    sm[t] = v;
    __syncthreads();
    for (int off = 1; off < 256; off <<= 1) {
        int x = 0;
        if (t >= off) x = sm[t - off];
        __syncthreads();
        if (t >= off) sm[t] += x;
        __syncthreads();
    }
    if (t < NB_SCAN) g_bsum[t] = sm[t] - v;
}

__global__ void k_scan3() {
    int i = blockIdx.x * blockDim.x + threadIdx.x;
    if (i < NN) {
        int r = g_rowptr[i] + g_bsum[i >> 9];
        g_rowptr[i] = r;
        g_cur[i] = r;
        g_dinv[i] = rsqrtf((float)g_ideg[i] + 1.0f);
    }
    if (i == 0) g_rowptr[NN] = NE;
}

__global__ void k_build(const void* __restrict__ ei) {
    int e = blockIdx.x * blockDim.x + threadIdx.x;
    if (e >= NE) return;
    int s, d;
    if (g_e32) {
        const int* p = (const int*)ei;
        s = p[e]; d = p[NE + e];
    } else {
        const long long* p = (const long long*)ei;
        s = (int)p[e]; d = (int)p[NE + e];
    }
    int pos = atomicAdd(&g_cur[d], 1);
    g_csrc[pos] = s;
    g_cnorm[pos] = g_dinv[s] * g_dinv[d];
}

// ---------------- W convert: f32 -> fp16 ----------------
__global__ void k_wconv(const float* __restrict__ W2, const float* __restrict__ W3,
                        const float* __restrict__ W4) {
    int i = blockIdx.x * blockDim.x + threadIdx.x;
    if (i < 16384)      g_W2[i] = __float2half_rn(W2[i]);
    else if (i < 32768) g_W3[i - 16384] = __float2half_rn(W3[i - 16384]);
    else if (i < 40960) g_W4[i - 32768] = __float2half_rn(W4[i - 32768]);
}

// ---------------- layer-1 input aggregation: A = Â x (dim 3) -------------
__global__ void k_agg3(const float* __restrict__ x) {
    int d = blockIdx.x * blockDim.x + threadIdx.x;
    if (d >= NN) return;
    int p = g_rowptr[d], pe = g_rowptr[d + 1];
    float a0 = 0.f, a1 = 0.f, a2 = 0.f;
    for (; p + 2 <= pe; p += 2) {
        int s0 = g_csrc[p], s1 = g_csrc[p + 1];
        float n0 = g_cnorm[p], n1 = g_cnorm[p + 1];
        a0 += n0 * x[s0 * 3]     + n1 * x[s1 * 3];
        a1 += n0 * x[s0 * 3 + 1] + n1 * x[s1 * 3 + 1];
        a2 += n0 * x[s0 * 3 + 2] + n1 * x[s1 * 3 + 2];
    }
    for (; p < pe; p++) {
        int s = g_csrc[p]; float nm = g_cnorm[p];
        a0 += nm * x[s * 3]; a1 += nm * x[s * 3 + 1]; a2 += nm * x[s * 3 + 2];
    }
    float dv = g_dinv[d], sl = dv * dv;
    g_bufA[d * 3 + 0] = a0 + sl * x[d * 3 + 0];
    g_bufA[d * 3 + 1] = a1 + sl * x[d * 3 + 1];
    g_bufA[d * 3 + 2] = a2 + sl * x[d * 3 + 2];
}

// ---------------- layer-1 GEMM: X2 = relu(A @ W1 + b1) -> fp16 -----------
__global__ void k_gemm3(const float* __restrict__ X, const float* __restrict__ W,
                        const float* __restrict__ B) {
    __shared__ float Ws[3 * 128];
    __shared__ float xs[32 * 3];
    const int tx = threadIdx.x;
    const int ty = threadIdx.y;
    const int tid = ty * 32 + tx;
    const int row0 = blockIdx.x * 32;
    for (int i = tid; i < 3 * 128; i += 128) Ws[i] = W[i];
    if (tid < 96) xs[tid] = X[(size_t)row0 * 3 + tid];
    __syncthreads();

    float4 wv[3];
    #pragma unroll
    for (int k = 0; k < 3; k++) wv[k] = ((const float4*)Ws)[k * 32 + tx];
    float4 bv = ((const float4*)B)[tx];

    #pragma unroll
    for (int r = 0; r < 8; r++) {
        int row = row0 + ty * 8 + r;
        float x0 = xs[(ty * 8 + r) * 3], x1 = xs[(ty * 8 + r) * 3 + 1],
              x2 = xs[(ty * 8 + r) * 3 + 2];
        float4 h;
        h.x = fmaxf(x0 * wv[0].x + x1 * wv[1].x + x2 * wv[2].x + bv.x, 0.f);
        h.y = fmaxf(x0 * wv[0].y + x1 * wv[1].y + x2 * wv[2].y + bv.y, 0.f);
        h.z = fmaxf(x0 * wv[0].z + x1 * wv[1].z + x2 * wv[2].z + bv.z, 0.f);
        h.w = fmaxf(x0 * wv[0].w + x1 * wv[1].w + x2 * wv[2].w + bv.w, 0.f);
        uint2 o;
        *(__half2*)&o.x = __floats2half2_rn(h.x, h.y);
        *(__half2*)&o.y = __floats2half2_rn(h.z, h.w);
        *(uint2*)((__half*)g_X + (size_t)row * 128 + tx * 4) = o;
    }
}

// ---------------- tensor-core GEMM: H = X @ W (fp16 in, fp16 out) --------
// block: 128 rows x DOUT cols, 256 threads (8 warps: 4 in M, 2 in N), KT=64
template<int DOUT>
__global__ __launch_bounds__(256) void k_gemm_tc(
    const __half* __restrict__ X, const __half* __restrict__ W,
    __half* __restrict__ H) {
    constexpr int KT = 64;
    constexpr int XS = 72;
    constexpr int WS = DOUT + 8;
    constexpr int NW = DOUT / 2;
    constexpr int NF = NW / 8;
    constexpr int WU4 = DOUT / 8;
    extern __shared__ __half smem[];
    __half* sX = smem;
    __half* sW = sX + 128 * XS;

    const int tid = threadIdx.x;
    const int wid = tid >> 5;
    const int lane = tid & 31;
    const int warpM = wid & 3;
    const int warpN = wid >> 2;
    const int row0 = blockIdx.x * 128;

    float acc[2][NF][4];
    #pragma unroll
    for (int mi = 0; mi < 2; mi++)
        #pragma unroll
        for (int ni = 0; ni < NF; ni++)
            acc[mi][ni][0] = acc[mi][ni][1] = acc[mi][ni][2] = acc[mi][ni][3] = 0.f;

    for (int k0 = 0; k0 < 128; k0 += KT) {
        #pragma unroll 2
        for (int i = tid; i < 128 * 8; i += 256) {
            int r = i >> 3, c = (i & 7) * 8;
            int gr = row0 + r;
            uint4 v = make_uint4(0, 0, 0, 0);
            if (gr < NN) v = *(const uint4*)(X + (size_t)gr * 128 + k0 + c);
            *(uint4*)(sX + r * XS + c) = v;
        }
        #pragma unroll 2
        for (int i = tid; i < KT * WU4; i += 256) {
            int r = i / WU4, c = (i % WU4) * 8;
            *(uint4*)(sW + r * WS + c) = *(const uint4*)(W + (size_t)(k0 + r) * DOUT + c);
        }
        __syncthreads();

        #pragma unroll
        for (int kk = 0; kk < KT; kk += 16) {
            uint32_t a[2][4], b[NF][2];
            #pragma unroll
            for (int mi = 0; mi < 2; mi++) {
                int r = warpM * 32 + mi * 16 + (lane & 15);
                int c = kk + ((lane >> 4) << 3);
                ldsm_x4(a[mi], sptr(sX + r * XS + c));
            }
            #pragma unroll
            for (int ni = 0; ni < NF; ni++) {
                int r = kk + (lane & 15);
                int c = warpN * NW + ni * 8;
                ldsm_x2t(b[ni], sptr(sW + r * WS + c));
            }
            #pragma unroll
            for (int mi = 0; mi < 2; mi++)
                #pragma unroll
                for (int ni = 0; ni < NF; ni++)
                    mma_f16(acc[mi][ni], a[mi], b[ni]);
        }
        __syncthreads();
    }

    #pragma unroll
    for (int mi = 0; mi < 2; mi++) {
        int r0 = row0 + warpM * 32 + mi * 16 + (lane >> 2);
        int c0 = warpN * NW + (lane & 3) * 2;
        #pragma unroll
        for (int ni = 0; ni < NF; ni++) {
            int c = c0 + ni * 8;
            if (r0 < NN) {
                __half2 h = __floats2half2_rn(acc[mi][ni][0], acc[mi][ni][1]);
                *(__half2*)(H + (size_t)r0 * DOUT + c) = h;
            }
            if (r0 + 8 < NN) {
                __half2 h = __floats2half2_rn(acc[mi][ni][2], acc[mi][ni][3]);
                *(__half2*)(H + (size_t)(r0 + 8) * DOUT + c) = h;
            }
        }
    }
}

// ---------------- CSR aggregation, dim 128 (fp16 gather, f32 accum) ------
// X' = relu( sum norm*H[src] + (1/deg)*H[d] + b ) -> fp16
__global__ void k_agg128(const __half* __restrict__ H, const float* __restrict__ B) {
    int warp = (blockIdx.x * blockDim.x + threadIdx.x) >> 5;
    int lane = threadIdx.x & 31;
    if (warp >= NN) return;
    int d = warp;
    const uint2* H2 = (const uint2*)H;   // 4 halves per lane, 32 lanes = 128
    int p = g_rowptr[d], pe = g_rowptr[d + 1];
    float4 acc = make_float4(0.f, 0.f, 0.f, 0.f);
    for (; p + 4 <= pe; p += 4) {
        int s0 = g_csrc[p],     s1 = g_csrc[p + 1];
        int s2 = g_csrc[p + 2], s3 = g_csrc[p + 3];
        float n0 = g_cnorm[p],     n1 = g_cnorm[p + 1];
        float n2 = g_cnorm[p + 2], n3 = g_cnorm[p + 3];
        uint2 u0 = H2[(size_t)s0 * 32 + lane];
        uint2 u1 = H2[(size_t)s1 * 32 + lane];
        uint2 u2 = H2[(size_t)s2 * 32 + lane];
        uint2 u3 = H2[(size_t)s3 * 32 + lane];
        acc_h4(acc, u0, n0); acc_h4(acc, u1, n1);
        acc_h4(acc, u2, n2); acc_h4(acc, u3, n3);
    }
    for (; p < pe; p++) {
        int s = g_csrc[p];
        acc_h4(acc, H2[(size_t)s * 32 + lane], g_cnorm[p]);
    }
    float dv = g_dinv[d], sl = dv * dv;
    acc_h4(acc, H2[(size_t)d * 32 + lane], sl);
    float4 bv = ((const float4*)B)[lane];
    acc.x = fmaxf(acc.x + bv.x, 0.f);
    acc.y = fmaxf(acc.y + bv.y, 0.f);
    acc.z = fmaxf(acc.z + bv.z, 0.f);
    acc.w = fmaxf(acc.w + bv.w, 0.f);
    uint2 o;
    *(__half2*)&o.x = __floats2half2_rn(acc.x, acc.y);
    *(__half2*)&o.y = __floats2half2_rn(acc.z, acc.w);
    *(uint2*)((__half*)g_X + (size_t)d * 128 + lane * 4) = o;
}

// ---------------- final agg (dim 64, fp16 gather) + mean-pool scatter ----
__global__ void k_agg64_pool(const __half* __restrict__ H, const float* __restrict__ B,
                             const void* __restrict__ batch) {
    int gt = blockIdx.x * blockDim.x + threadIdx.x;
    int d = gt >> 4;
    int c = gt & 15;
    if (d >= NN) return;
    const uint2* H2 = (const uint2*)H;
    int p = g_rowptr[d], pe = g_rowptr[d + 1];
    float4 acc = make_float4(0.f, 0.f, 0.f, 0.f);
    for (; p + 4 <= pe; p += 4) {
        int s0 = g_csrc[p],     s1 = g_csrc[p + 1];
        int s2 = g_csrc[p + 2], s3 = g_csrc[p + 3];
        float n0 = g_cnorm[p],     n1 = g_cnorm[p + 1];
        float n2 = g_cnorm[p + 2], n3 = g_cnorm[p + 3];
        acc_h4(acc, H2[(size_t)s0 * 16 + c], n0);
        acc_h4(acc, H2[(size_t)s1 * 16 + c], n1);
        acc_h4(acc, H2[(size_t)s2 * 16 + c], n2);
        acc_h4(acc, H2[(size_t)s3 * 16 + c], n3);
    }
    for (; p < pe; p++) {
        acc_h4(acc, H2[(size_t)g_csrc[p] * 16 + c], g_cnorm[p]);
    }
    float dv = g_dinv[d], sl = dv * dv;
    acc_h4(acc, H2[(size_t)d * 16 + c], sl);
    float4 bv = ((const float4*)B)[c];
    acc.x += bv.x; acc.y += bv.y; acc.z += bv.z; acc.w += bv.w;
    int g;
    if (g_b32) g = ((const int*)batch)[d];
    else       g = (int)((const long long*)batch)[d];
    red_add_v4(&g_pool[g * 64 + c * 4], acc.x, acc.y, acc.z, acc.w);
    if (c == 0) atomicAdd(&g_cnt[g], 1.0f);
}

// ---------------- final MLP ----------------
__global__ void k_mlp(const float* __restrict__ Wl1, const float* __restrict__ bl1,
                      const float* __restrict__ Wl2, const float* __restrict__ bl2,
                      float* __restrict__ out) {
    __shared__ float mean[64];
    __shared__ float hid[32];
    int g = blockIdx.x;
    int t = threadIdx.x;
    float cnt = fmaxf(g_cnt[g], 1.0f);
    mean[t] = g_pool[g * 64 + t] / cnt;
    __syncthreads();
    if (t < 32) {
        float s = bl1[t];
        #pragma unroll 8
        for (int k = 0; k < 64; k++) s += mean[k] * Wl1[k * 32 + t];
        hid[t] = fmaxf(s, 0.0f);
    }
    __syncthreads();
    if (t < 9) {
        float s = bl2[t];
        #pragma unroll 8
        for (int k = 0; k < 32; k++) s += hid[k] * Wl2[k * 9 + t];
        out[g * 9 + t] = s;
    }
}

// ---------------- launch ----------------
extern "C" void kernel_launch(void* const* d_in, const int* in_sizes, int n_in,
                              void* d_out, int out_size) {
    const float* x     = (const float*)d_in[0];
    const void*  ei    = d_in[1];
    const void*  batch = d_in[2];
    const float* W1 = (const float*)d_in[3];  const float* b1 = (const float*)d_in[4];
    const float* W2 = (const float*)d_in[5];  const float* b2 = (const float*)d_in[6];
    const float* W3 = (const float*)d_in[7];  const float* b3 = (const float*)d_in[8];
    const float* W4 = (const float*)d_in[9];  const float* b4 = (const float*)d_in[10];
    const float* Wl1 = (const float*)d_in[11]; const float* bl1 = (const float*)d_in[12];
    const float* Wl2 = (const float*)d_in[13]; const float* bl2 = (const float*)d_in[14];
    float* out = (float*)d_out;

    float* bufA;
    __half *bufH, *bufX, *w2, *w3, *w4;
    cudaGetSymbolAddress((void**)&bufH, g_H);
    cudaGetSymbolAddress((void**)&bufX, g_X);
    cudaGetSymbolAddress((void**)&bufA, g_bufA);
    cudaGetSymbolAddress((void**)&w2, g_W2);
    cudaGetSymbolAddress((void**)&w3, g_W3);
    cudaGetSymbolAddress((void**)&w4, g_W4);

    const int smem128 = (128 * 72 + 64 * 136) * 2;   // 35840
    const int smem64  = (128 * 72 + 64 * 72) * 2;    // 27648

    // preprocessing
    k_detect<<<1, 256>>>((const unsigned*)ei, (const unsigned*)batch);
    k_zero<<<(NN + 255) / 256, 256>>>();
    k_deg<<<NE / 256, 256>>>(ei);
    k_scan1<<<NB_SCAN, 512>>>();
    k_scan2<<<1, 256>>>();
    k_scan3<<<(NN + 255) / 256, 256>>>();
    k_build<<<NE / 256, 256>>>(ei);
    k_wconv<<<160, 256>>>(W2, W3, W4);

    const int GTC = (NN + 127) / 128;   // 782

    // layer 1: A = Â x (dim 3), X2 = relu(A @ W1 + b1) -> fp16
    k_agg3<<<(NN + 255) / 256, 256>>>(x);
    k_gemm3<<<NN / 32, dim3(32, 4)>>>(bufA, W1, b1);

    // layer 2
    k_gemm_tc<128><<<GTC, 256, smem128>>>(bufX, w2, bufH);
    k_agg128<<<12500, 256>>>(bufH, b2);
    // layer 3
    k_gemm_tc<128><<<GTC, 256, smem128>>>(bufX, w3, bufH);
    k_agg128<<<12500, 256>>>(bufH, b3);
    // layer 4
    k_gemm_tc<64><<<GTC, 256, smem64>>>(bufX, w4, bufH);
    k_agg64_pool<<<(NN * 16) / 256, 256>>>(bufH, b4, batch);

    k_mlp<<<NG, 64>>>(Wl1, bl1, Wl2, bl2, out);
}

// round 8
// speedup vs baseline: 4.0006x; 1.0340x over previous
#include <cuda_runtime.h>
#include <cuda_fp16.h>
#include <cstdint>
#include <math.h>

#define NN 100000
#define NE 1600000
#define NG 512
#define NB_SCAN 196   // ceil(NN/512)

// ---------------- device scratch (static, no allocations) ----------------
__device__ __align__(16) __half g_H[NN * 128];   // GEMM out (fp16)
__device__ __align__(16) __half g_X[NN * 128];   // activations (fp16)
__device__ __align__(16) float g_bufA[NN * 3];
__device__ __align__(16) __half g_W2[16384], g_W3[16384], g_W4[8192];
__device__ int   g_ideg[NN];
__device__ float g_dinv[NN];
__device__ __align__(16) int   g_csrc[NE];
__device__ __align__(16) float g_cnorm[NE];
__device__ int   g_rowptr[NN + 1];
__device__ int   g_cur[NN];
__device__ int   g_bsum[256];
__device__ __align__(16) float g_pool[NG * 64];
__device__ float g_cnt[NG];
__device__ int   g_e32;
__device__ int   g_b32;

// ---------------- helpers ----------------
__device__ __forceinline__ void red_add_v4(float* p, float a, float b, float c, float d) {
    asm volatile("red.global.add.v4.f32 [%0], {%1,%2,%3,%4};"
                 :: "l"(p), "f"(a), "f"(b), "f"(c), "f"(d) : "memory");
}
__device__ __forceinline__ uint32_t sptr(const void* p) {
    return (uint32_t)__cvta_generic_to_shared(p);
}
__device__ __forceinline__ void cp16(uint32_t dst, const void* src, bool valid) {
    int b = valid ? 16 : 0;
    asm volatile("cp.async.cg.shared.global [%0], [%1], 16, %2;"
                 :: "r"(dst), "l"(src), "r"(b));
}
__device__ __forceinline__ void cp_commit() {
    asm volatile("cp.async.commit_group;");
}
template<int N>
__device__ __forceinline__ void cp_wait() {
    asm volatile("cp.async.wait_group %0;" :: "n"(N));
}
__device__ __forceinline__ void ldsm_x4(uint32_t (&r)[4], uint32_t a) {
    asm volatile("ldmatrix.sync.aligned.m8n8.x4.shared.b16 {%0,%1,%2,%3}, [%4];"
                 : "=r"(r[0]), "=r"(r[1]), "=r"(r[2]), "=r"(r[3]) : "r"(a));
}
__device__ __forceinline__ void ldsm_x2t(uint32_t (&r)[2], uint32_t a) {
    asm volatile("ldmatrix.sync.aligned.m8n8.x2.trans.shared.b16 {%0,%1}, [%2];"
                 : "=r"(r[0]), "=r"(r[1]) : "r"(a));
}
__device__ __forceinline__ void mma_f16(float (&d)[4], const uint32_t (&a)[4],
                                        const uint32_t (&b)[2]) {
    asm volatile("mma.sync.aligned.m16n8k16.row.col.f32.f16.f16.f32 "
                 "{%0,%1,%2,%3}, {%4,%5,%6,%7}, {%8,%9}, {%0,%1,%2,%3};"
                 : "+f"(d[0]), "+f"(d[1]), "+f"(d[2]), "+f"(d[3])
                 : "r"(a[0]), "r"(a[1]), "r"(a[2]), "r"(a[3]), "r"(b[0]), "r"(b[1]));
}
__device__ __forceinline__ void acc_h4(float4& acc, uint2 u, float n) {
    float2 a = __half22float2(*(__half2*)&u.x);
    float2 b = __half22float2(*(__half2*)&u.y);
    acc.x += n * a.x; acc.y += n * a.y; acc.z += n * b.x; acc.w += n * b.y;
}

// ---------------- dtype detection (int32 vs int64 index arrays) ----------
__global__ void k_detect(const unsigned* __restrict__ e, const unsigned* __restrict__ b) {
    __shared__ unsigned se[256], sb[256];
    int t = threadIdx.x;
    unsigned ae = 0, ab = 0;
    const int SE = (2 * NE) / 4096;
    const int SB = NN / 4096;
    for (int i = t; i < 4096; i += 256) {
        ae |= e[(i * SE) | 1];
        ab |= b[(i * SB) | 1];
    }
    se[t] = ae; sb[t] = ab;
    __syncthreads();
    for (int s = 128; s; s >>= 1) {
        if (t < s) { se[t] |= se[t + s]; sb[t] |= sb[t + s]; }
        __syncthreads();
    }
    if (t == 0) { g_e32 = (se[0] != 0); g_b32 = (sb[0] != 0); }
}

__global__ void k_zero() {
    int i = blockIdx.x * blockDim.x + threadIdx.x;
    if (i < NN) g_ideg[i] = 0;
    if (i < NG * 64) g_pool[i] = 0.0f;
    if (i < NG) g_cnt[i] = 0.0f;
}

__global__ void k_deg(const void* __restrict__ ei) {
    int e = blockIdx.x * blockDim.x + threadIdx.x;
    if (e >= NE) return;
    int d;
    if (g_e32) d = ((const int*)ei)[NE + e];
    else       d = (int)((const long long*)ei)[NE + e];
    atomicAdd(&g_ideg[d], 1);
}

// ---------------- 2-level exclusive scan of degrees -> rowptr ------------
__global__ void k_scan1() {
    __shared__ int sm[512];
    int t = threadIdx.x;
    int i = blockIdx.x * 512 + t;
    int v = (i < NN) ? g_ideg[i] : 0;
    sm[t] = v;
    __syncthreads();
    for (int off = 1; off < 512; off <<= 1) {
        int x = 0;
        if (t >= off) x = sm[t - off];
        __syncthreads();
        if (t >= off) sm[t] += x;
        __syncthreads();
    }
    if (i < NN) g_rowptr[i] = sm[t] - v;
    if (t == 511) g_bsum[blockIdx.x] = sm[511];
}

__global__ void k_scan2() {
    __shared__ int sm[256];
    int t = threadIdx.x;
    int v = (t < NB_SCAN) ? g_bsum[t] : 0;
    sm[t] = v;
    __syncthreads();
    for (int off = 1; off < 256; off <<= 1) {
        int x = 0;
        if (t >= off) x = sm[t - off];
        __syncthreads();
        if (t >= off) sm[t] += x;
        __syncthreads();
    }
    if (t < NB_SCAN) g_bsum[t] = sm[t] - v;
}

__global__ void k_scan3() {
    int i = blockIdx.x * blockDim.x + threadIdx.x;
    if (i < NN) {
        int r = g_rowptr[i] + g_bsum[i >> 9];
        g_rowptr[i] = r;
        g_cur[i] = r;
        g_dinv[i] = rsqrtf((float)g_ideg[i] + 1.0f);
    }
    if (i == 0) g_rowptr[NN] = NE;
}

__global__ void k_build(const void* __restrict__ ei) {
    int e = blockIdx.x * blockDim.x + threadIdx.x;
    if (e >= NE) return;
    int s, d;
    if (g_e32) {
        const int* p = (const int*)ei;
        s = p[e]; d = p[NE + e];
    } else {
        const long long* p = (const long long*)ei;
        s = (int)p[e]; d = (int)p[NE + e];
    }
    int pos = atomicAdd(&g_cur[d], 1);
    g_csrc[pos] = s;
    g_cnorm[pos] = g_dinv[s] * g_dinv[d];
}

// ---------------- W convert: f32 -> fp16 ----------------
__global__ void k_wconv(const float* __restrict__ W2, const float* __restrict__ W3,
                        const float* __restrict__ W4) {
    int i = blockIdx.x * blockDim.x + threadIdx.x;
    if (i < 16384)      g_W2[i] = __float2half_rn(W2[i]);
    else if (i < 32768) g_W3[i - 16384] = __float2half_rn(W3[i - 16384]);
    else if (i < 40960) g_W4[i - 32768] = __float2half_rn(W4[i - 32768]);
}

// ---------------- layer-1 input aggregation: A = Â x (dim 3) -------------
__global__ void k_agg3(const float* __restrict__ x) {
    int d = blockIdx.x * blockDim.x + threadIdx.x;
    if (d >= NN) return;
    int p = g_rowptr[d], pe = g_rowptr[d + 1];
    float a0 = 0.f, a1 = 0.f, a2 = 0.f;
    for (; p + 2 <= pe; p += 2) {
        int s0 = g_csrc[p], s1 = g_csrc[p + 1];
        float n0 = g_cnorm[p], n1 = g_cnorm[p + 1];
        a0 += n0 * x[s0 * 3]     + n1 * x[s1 * 3];
        a1 += n0 * x[s0 * 3 + 1] + n1 * x[s1 * 3 + 1];
        a2 += n0 * x[s0 * 3 + 2] + n1 * x[s1 * 3 + 2];
    }
    for (; p < pe; p++) {
        int s = g_csrc[p]; float nm = g_cnorm[p];
        a0 += nm * x[s * 3]; a1 += nm * x[s * 3 + 1]; a2 += nm * x[s * 3 + 2];
    }
    float dv = g_dinv[d], sl = dv * dv;
    g_bufA[d * 3 + 0] = a0 + sl * x[d * 3 + 0];
    g_bufA[d * 3 + 1] = a1 + sl * x[d * 3 + 1];
    g_bufA[d * 3 + 2] = a2 + sl * x[d * 3 + 2];
}

// ---------------- layer-1 GEMM: X2 = relu(A @ W1 + b1) -> fp16 -----------
__global__ void k_gemm3(const float* __restrict__ X, const float* __restrict__ W,
                        const float* __restrict__ B) {
    __shared__ float Ws[3 * 128];
    __shared__ float xs[32 * 3];
    const int tx = threadIdx.x;
    const int ty = threadIdx.y;
    const int tid = ty * 32 + tx;
    const int row0 = blockIdx.x * 32;
    for (int i = tid; i < 3 * 128; i += 128) Ws[i] = W[i];
    if (tid < 96) xs[tid] = X[(size_t)row0 * 3 + tid];
    __syncthreads();

    float4 wv[3];
    #pragma unroll
    for (int k = 0; k < 3; k++) wv[k] = ((const float4*)Ws)[k * 32 + tx];
    float4 bv = ((const float4*)B)[tx];

    #pragma unroll
    for (int r = 0; r < 8; r++) {
        int row = row0 + ty * 8 + r;
        float x0 = xs[(ty * 8 + r) * 3], x1 = xs[(ty * 8 + r) * 3 + 1],
              x2 = xs[(ty * 8 + r) * 3 + 2];
        float4 h;
        h.x = fmaxf(x0 * wv[0].x + x1 * wv[1].x + x2 * wv[2].x + bv.x, 0.f);
        h.y = fmaxf(x0 * wv[0].y + x1 * wv[1].y + x2 * wv[2].y + bv.y, 0.f);
        h.z = fmaxf(x0 * wv[0].z + x1 * wv[1].z + x2 * wv[2].z + bv.z, 0.f);
        h.w = fmaxf(x0 * wv[0].w + x1 * wv[1].w + x2 * wv[2].w + bv.w, 0.f);
        uint2 o;
        *(__half2*)&o.x = __floats2half2_rn(h.x, h.y);
        *(__half2*)&o.y = __floats2half2_rn(h.z, h.w);
        *(uint2*)((__half*)g_X + (size_t)row * 128 + tx * 4) = o;
    }
}

// ---------------- tensor-core GEMM, cp.async 2-stage: H = X @ W ----------
// block: 128 rows x DOUT cols, 256 threads (8 warps: 4 in M, 2 in N), KT=64
template<int DOUT>
__global__ __launch_bounds__(256) void k_gemm_tc(
    const __half* __restrict__ X, const __half* __restrict__ W,
    __half* __restrict__ H) {
    constexpr int KT = 64;
    constexpr int XS = 72;
    constexpr int WS = DOUT + 8;
    constexpr int NW = DOUT / 2;
    constexpr int NF = NW / 8;
    constexpr int WU4 = DOUT / 8;
    constexpr int STAGE = 128 * XS + KT * WS;
    extern __shared__ __half smem[];

    const int tid = threadIdx.x;
    const int wid = tid >> 5;
    const int lane = tid & 31;
    const int warpM = wid & 3;
    const int warpN = wid >> 2;
    const int row0 = blockIdx.x * 128;

    auto load_stage = [&](int s, int k0) {
        __half* sX = smem + s * STAGE;
        __half* sW = sX + 128 * XS;
        #pragma unroll
        for (int i = tid; i < 128 * 8; i += 256) {
            int r = i >> 3, c = (i & 7) * 8;
            int gr = row0 + r;
            bool valid = gr < NN;
            int gsrc = valid ? gr : (NN - 1);   // clamp: address always in-bounds
            cp16(sptr(sX + r * XS + c), X + (size_t)gsrc * 128 + k0 + c, valid);
        }
        #pragma unroll
        for (int i = tid; i < KT * WU4; i += 256) {
            int r = i / WU4, c = (i % WU4) * 8;
            cp16(sptr(sW + r * WS + c), W + (size_t)(k0 + r) * DOUT + c, true);
        }
        cp_commit();
    };

    float acc[2][NF][4];
    #pragma unroll
    for (int mi = 0; mi < 2; mi++)
        #pragma unroll
        for (int ni = 0; ni < NF; ni++)
            acc[mi][ni][0] = acc[mi][ni][1] = acc[mi][ni][2] = acc[mi][ni][3] = 0.f;

    load_stage(0, 0);
    load_stage(1, KT);

    #pragma unroll
    for (int it = 0; it < 2; it++) {
        if (it == 0) cp_wait<1>(); else cp_wait<0>();
        __syncthreads();
        __half* sX = smem + it * STAGE;
        __half* sW = sX + 128 * XS;
        #pragma unroll
        for (int kk = 0; kk < KT; kk += 16) {
            uint32_t a[2][4], b[NF][2];
            #pragma unroll
            for (int mi = 0; mi < 2; mi++) {
                int r = warpM * 32 + mi * 16 + (lane & 15);
                int c = kk + ((lane >> 4) << 3);
                ldsm_x4(a[mi], sptr(sX + r * XS + c));
            }
            #pragma unroll
            for (int ni = 0; ni < NF; ni++) {
                int r = kk + (lane & 15);
                int c = warpN * NW + ni * 8;
                ldsm_x2t(b[ni], sptr(sW + r * WS + c));
            }
            #pragma unroll
            for (int mi = 0; mi < 2; mi++)
                #pragma unroll
                for (int ni = 0; ni < NF; ni++)
                    mma_f16(acc[mi][ni], a[mi], b[ni]);
        }
    }

    #pragma unroll
    for (int mi = 0; mi < 2; mi++) {
        int r0 = row0 + warpM * 32 + mi * 16 + (lane >> 2);
        int c0 = warpN * NW + (lane & 3) * 2;
        #pragma unroll
        for (int ni = 0; ni < NF; ni++) {
            int c = c0 + ni * 8;
            if (r0 < NN) {
                __half2 h = __floats2half2_rn(acc[mi][ni][0], acc[mi][ni][1]);
                *(__half2*)(H + (size_t)r0 * DOUT + c) = h;
            }
            if (r0 + 8 < NN) {
                __half2 h = __floats2half2_rn(acc[mi][ni][2], acc[mi][ni][3]);
                *(__half2*)(H + (size_t)(r0 + 8) * DOUT + c) = h;
            }
        }
    }
}

// ---------------- CSR aggregation, dim 128 (fp16 gather, f32 accum) ------
// X' = relu( sum norm*H[src] + (1/deg)*H[d] + b ) -> fp16
__global__ void k_agg128(const __half* __restrict__ H, const float* __restrict__ B) {
    int warp = (blockIdx.x * blockDim.x + threadIdx.x) >> 5;
    int lane = threadIdx.x & 31;
    if (warp >= NN) return;
    int d = warp;
    const uint2* H2 = (const uint2*)H;   // 4 halves per lane, 32 lanes = 128
    int p = g_rowptr[d], pe = g_rowptr[d + 1];
    float4 acc = make_float4(0.f, 0.f, 0.f, 0.f);
    while (p < pe && (p & 3)) {
        acc_h4(acc, H2[(size_t)g_csrc[p] * 32 + lane], g_cnorm[p]);
        p++;
    }
    for (; p + 8 <= pe; p += 8) {
        int4   i0 = *(const int4*)&g_csrc[p];
        int4   i1 = *(const int4*)&g_csrc[p + 4];
        float4 n0 = *(const float4*)&g_cnorm[p];
        float4 n1 = *(const float4*)&g_cnorm[p + 4];
        uint2 u0 = H2[(size_t)i0.x * 32 + lane];
        uint2 u1 = H2[(size_t)i0.y * 32 + lane];
        uint2 u2 = H2[(size_t)i0.z * 32 + lane];
        uint2 u3 = H2[(size_t)i0.w * 32 + lane];
        uint2 u4 = H2[(size_t)i1.x * 32 + lane];
        uint2 u5 = H2[(size_t)i1.y * 32 + lane];
        uint2 u6 = H2[(size_t)i1.z * 32 + lane];
        uint2 u7 = H2[(size_t)i1.w * 32 + lane];
        acc_h4(acc, u0, n0.x); acc_h4(acc, u1, n0.y);
        acc_h4(acc, u2, n0.z); acc_h4(acc, u3, n0.w);
        acc_h4(acc, u4, n1.x); acc_h4(acc, u5, n1.y);
        acc_h4(acc, u6, n1.z); acc_h4(acc, u7, n1.w);
    }
    if (p + 4 <= pe) {
        int4   i0 = *(const int4*)&g_csrc[p];
        float4 n0 = *(const float4*)&g_cnorm[p];
        uint2 u0 = H2[(size_t)i0.x * 32 + lane];
        uint2 u1 = H2[(size_t)i0.y * 32 + lane];
        uint2 u2 = H2[(size_t)i0.z * 32 + lane];
        uint2 u3 = H2[(size_t)i0.w * 32 + lane];
        acc_h4(acc, u0, n0.x); acc_h4(acc, u1, n0.y);
        acc_h4(acc, u2, n0.z); acc_h4(acc, u3, n0.w);
        p += 4;
    }
    for (; p < pe; p++)
        acc_h4(acc, H2[(size_t)g_csrc[p] * 32 + lane], g_cnorm[p]);

    float dv = g_dinv[d], sl = dv * dv;
    acc_h4(acc, H2[(size_t)d * 32 + lane], sl);
    float4 bv = ((const float4*)B)[lane];
    acc.x = fmaxf(acc.x + bv.x, 0.f);
    acc.y = fmaxf(acc.y + bv.y, 0.f);
    acc.z = fmaxf(acc.z + bv.z, 0.f);
    acc.w = fmaxf(acc.w + bv.w, 0.f);
    uint2 o;
    *(__half2*)&o.x = __floats2half2_rn(acc.x, acc.y);
    *(__half2*)&o.y = __floats2half2_rn(acc.z, acc.w);
    *(uint2*)((__half*)g_X + (size_t)d * 128 + lane * 4) = o;
}

// ---------------- final agg (dim 64, fp16 gather) + mean-pool scatter ----
__global__ void k_agg64_pool(const __half* __restrict__ H, const float* __restrict__ B,
                             const void* __restrict__ batch) {
    int gt = blockIdx.x * blockDim.x + threadIdx.x;
    int d = gt >> 4;
    int c = gt & 15;
    if (d >= NN) return;
    const uint2* H2 = (const uint2*)H;
    int p = g_rowptr[d], pe = g_rowptr[d + 1];
    float4 acc = make_float4(0.f, 0.f, 0.f, 0.f);
    while (p < pe && (p & 3)) {
        acc_h4(acc, H2[(size_t)g_csrc[p] * 16 + c], g_cnorm[p]);
        p++;
    }
    for (; p + 8 <= pe; p += 8) {
        int4   i0 = *(const int4*)&g_csrc[p];
        int4   i1 = *(const int4*)&g_csrc[p + 4];
        float4 n0 = *(const float4*)&g_cnorm[p];
        float4 n1 = *(const float4*)&g_cnorm[p + 4];
        uint2 u0 = H2[(size_t)i0.x * 16 + c];
        uint2 u1 = H2[(size_t)i0.y * 16 + c];
        uint2 u2 = H2[(size_t)i0.z * 16 + c];
        uint2 u3 = H2[(size_t)i0.w * 16 + c];
        uint2 u4 = H2[(size_t)i1.x * 16 + c];
        uint2 u5 = H2[(size_t)i1.y * 16 + c];
        uint2 u6 = H2[(size_t)i1.z * 16 + c];
        uint2 u7 = H2[(size_t)i1.w * 16 + c];
        acc_h4(acc, u0, n0.x); acc_h4(acc, u1, n0.y);
        acc_h4(acc, u2, n0.z); acc_h4(acc, u3, n0.w);
        acc_h4(acc, u4, n1.x); acc_h4(acc, u5, n1.y);
        acc_h4(acc, u6, n1.z); acc_h4(acc, u7, n1.w);
    }
    if (p + 4 <= pe) {
        int4   i0 = *(const int4*)&g_csrc[p];
        float4 n0 = *(const float4*)&g_cnorm[p];
        uint2 u0 = H2[(size_t)i0.x * 16 + c];
        uint2 u1 = H2[(size_t)i0.y * 16 + c];
        uint2 u2 = H2[(size_t)i0.z * 16 + c];
        uint2 u3 = H2[(size_t)i0.w * 16 + c];
        acc_h4(acc, u0, n0.x); acc_h4(acc, u1, n0.y);
        acc_h4(acc, u2, n0.z); acc_h4(acc, u3, n0.w);
        p += 4;
    }
    for (; p < pe; p++)
        acc_h4(acc, H2[(size_t)g_csrc[p] * 16 + c], g_cnorm[p]);

    float dv = g_dinv[d], sl = dv * dv;
    acc_h4(acc, H2[(size_t)d * 16 + c], sl);
    float4 bv = ((const float4*)B)[c];
    acc.x += bv.x; acc.y += bv.y; acc.z += bv.z; acc.w += bv.w;
    int g;
    if (g_b32) g = ((const int*)batch)[d];
    else       g = (int)((const long long*)batch)[d];
    red_add_v4(&g_pool[g * 64 + c * 4], acc.x, acc.y, acc.z, acc.w);
    if (c == 0) atomicAdd(&g_cnt[g], 1.0f);
}

// ---------------- final MLP ----------------
__global__ void k_mlp(const float* __restrict__ Wl1, const float* __restrict__ bl1,
                      const float* __restrict__ Wl2, const float* __restrict__ bl2,
                      float* __restrict__ out) {
    __shared__ float mean[64];
    __shared__ float hid[32];
    int g = blockIdx.x;
    int t = threadIdx.x;
    float cnt = fmaxf(g_cnt[g], 1.0f);
    mean[t] = g_pool[g * 64 + t] / cnt;
    __syncthreads();
    if (t < 32) {
        float s = bl1[t];
        #pragma unroll 8
        for (int k = 0; k < 64; k++) s += mean[k] * Wl1[k * 32 + t];
        hid[t] = fmaxf(s, 0.0f);
    }
    __syncthreads();
    if (t < 9) {
        float s = bl2[t];
        #pragma unroll 8
        for (int k = 0; k < 32; k++) s += hid[k] * Wl2[k * 9 + t];
        out[g * 9 + t] = s;
    }
}

// ---------------- launch ----------------
extern "C" void kernel_launch(void* const* d_in, const int* in_sizes, int n_in,
                              void* d_out, int out_size) {
    const float* x     = (const float*)d_in[0];
    const void*  ei    = d_in[1];
    const void*  batch = d_in[2];
    const float* W1 = (const float*)d_in[3];  const float* b1 = (const float*)d_in[4];
    const float* W2 = (const float*)d_in[5];  const float* b2 = (const float*)d_in[6];
    const float* W3 = (const float*)d_in[7];  const float* b3 = (const float*)d_in[8];
    const float* W4 = (const float*)d_in[9];  const float* b4 = (const float*)d_in[10];
    const float* Wl1 = (const float*)d_in[11]; const float* bl1 = (const float*)d_in[12];
    const float* Wl2 = (const float*)d_in[13]; const float* bl2 = (const float*)d_in[14];
    float* out = (float*)d_out;

    float* bufA;
    __half *bufH, *bufX, *w2, *w3, *w4;
    cudaGetSymbolAddress((void**)&bufH, g_H);
    cudaGetSymbolAddress((void**)&bufX, g_X);
    cudaGetSymbolAddress((void**)&bufA, g_bufA);
    cudaGetSymbolAddress((void**)&w2, g_W2);
    cudaGetSymbolAddress((void**)&w3, g_W3);
    cudaGetSymbolAddress((void**)&w4, g_W4);

    const int smem128 = 2 * (128 * 72 + 64 * 136) * 2;   // 71680
    const int smem64  = 2 * (128 * 72 + 64 * 72) * 2;    // 55296
    cudaFuncSetAttribute((const void*)k_gemm_tc<128>,
                         cudaFuncAttributeMaxDynamicSharedMemorySize, smem128);
    cudaFuncSetAttribute((const void*)k_gemm_tc<64>,
                         cudaFuncAttributeMaxDynamicSharedMemorySize, smem64);

    // preprocessing
    k_detect<<<1, 256>>>((const unsigned*)ei, (const unsigned*)batch);
    k_zero<<<(NN + 255) / 256, 256>>>();
    k_deg<<<NE / 256, 256>>>(ei);
    k_scan1<<<NB_SCAN, 512>>>();
    k_scan2<<<1, 256>>>();
    k_scan3<<<(NN + 255) / 256, 256>>>();
    k_build<<<NE / 256, 256>>>(ei);
    k_wconv<<<160, 256>>>(W2, W3, W4);

    const int GTC = (NN + 127) / 128;   // 782

    // layer 1: A = Â x (dim 3), X2 = relu(A @ W1 + b1) -> fp16
    k_agg3<<<(NN + 255) / 256, 256>>>(x);
    k_gemm3<<<NN / 32, dim3(32, 4)>>>(bufA, W1, b1);

    // layer 2
    k_gemm_tc<128><<<GTC, 256, smem128>>>(bufX, w2, bufH);
    k_agg128<<<12500, 256>>>(bufH, b2);
    // layer 3
    k_gemm_tc<128><<<GTC, 256, smem128>>>(bufX, w3, bufH);
    k_agg128<<<12500, 256>>>(bufH, b3);
    // layer 4
    k_gemm_tc<64><<<GTC, 256, smem64>>>(bufX, w4, bufH);
    k_agg64_pool<<<(NN * 16) / 256, 256>>>(bufH, b4, batch);

    k_mlp<<<NG, 64>>>(Wl1, bl1, Wl2, bl2, out);
}